// round 6
// baseline (speedup 1.0000x reference)
#include <cuda_runtime.h>
#include <cuda_fp16.h>
#include <math.h>
#include <stdint.h>

#define B  4096
#define T  28
#define H  128
#define F0 28
#define NL 10
#define NC 10
#define BT 16           // batch rows per CTA
#define CTAS (B / BT)   // 256
#define NT 256          // 8 warps

// Static device buffers. Packed activations per CTA per t: 1024 hi + 1024 lo
// words (f16x2) in m16n8k16 A-fragment order. Single buffer (CTA-private,
// overwritten in place layer by layer).
__device__ uint32_t g_act[(size_t)CTAS * T * 2048];
__device__ float    g_xp [(size_t)B * T * H];      // fp32 xp, fragment order

// ---------------------------------------------------------------------------
// helpers
// ---------------------------------------------------------------------------
__device__ __forceinline__ uint32_t pack2(__half a, __half b) {
    __half2 h = __halves2half2(a, b);
    return *reinterpret_cast<uint32_t*>(&h);
}
__device__ __forceinline__ void split16(float x, __half &hi, __half &lo) {
    hi = __float2half_rn(x);
    lo = __float2half_rn(x - __half2float(hi));
}
__device__ __forceinline__ void mma16(float c[4], uint4 a, const uint32_t b[2]) {
    asm volatile("mma.sync.aligned.m16n8k16.row.col.f32.f16.f16.f32 "
        "{%0,%1,%2,%3}, {%4,%5,%6,%7}, {%8,%9}, {%0,%1,%2,%3};"
        : "+f"(c[0]), "+f"(c[1]), "+f"(c[2]), "+f"(c[3])
        : "r"(a.x), "r"(a.y), "r"(a.z), "r"(a.w), "r"(b[0]), "r"(b[1]));
}
__device__ __forceinline__ float fast_tanh(float x) {
    float e; asm("ex2.approx.f32 %0, %1;" : "=f"(e) : "f"(x * 2.8853900817779268f));
    float r; asm("rcp.approx.f32 %0, %1;" : "=f"(r) : "f"(e + 1.0f));
    return fmaf(-2.0f, r, 1.0f);
}
// A-fragment word index for element (rl 0..15, kk 0..15) of one m16k16 tile
__device__ __forceinline__ int awidx(int rl, int kk) {
    int lane = ((rl & 7) << 2) | ((kk & 7) >> 1);
    int reg  = ((kk & 8) >> 2) | (rl >> 3);
    return lane * 4 + reg;               // half select = kk & 1
}

// ---------------------------------------------------------------------------
// Persistent whole-network kernel: each CTA runs its 16 batch rows through
// all 10 layers + FC. No inter-CTA synchronization anywhere.
// Warp w = n-slice [16w, 16w+16); single m16 tile per CTA.
// ---------------------------------------------------------------------------
__global__ void __launch_bounds__(NT, 2)
rnn_net(const float* __restrict__ x,      // [B, T, F0]
        const float* __restrict__ Wih0,   // [H, F0]
        const float* __restrict__ WihR,   // [NL-1, H, H]
        const float* __restrict__ Whh,    // [NL, H, H]
        const float* __restrict__ bih,    // [NL, H]
        const float* __restrict__ bhh,    // [NL, H]
        const float* __restrict__ fcW,    // [NC, H]
        const float* __restrict__ fcb,    // [NC]
        float*       __restrict__ out,    // [B, NC]
        uint32_t*    __restrict__ actg,
        float*       __restrict__ xpg)
{
    __shared__ __align__(16) uint32_t AsH[2048];   // [2 buf][1024]
    __shared__ __align__(16) uint32_t AsL[2048];
    __shared__ float hsm[BT][H];                   // final h for FC

    const int tid  = threadIdx.x;
    const int lane = tid & 31;
    const int ns   = tid >> 5;
    const int grp  = lane >> 2;
    const int tig  = lane & 3;
    const int b0   = blockIdx.x * BT;
    float*    xp  = xpg  + (size_t)blockIdx.x * (T * 2048);
    uint32_t* act = actg + (size_t)blockIdx.x * (T * 2048);

    uint32_t Bhi[8][2][2], Blo[8][2][2];

    for (int l = 0; l < NL; ++l) {
        const int FIN = (l == 0) ? F0 : H;
        const int KC  = (l == 0) ? 2 : 8;
        const float* Wih = (l == 0) ? Wih0 : (WihR + (size_t)(l - 1) * H * H);
        const float* bi  = bih + (size_t)l * H;
        const float* bh  = bhh + (size_t)l * H;

        // ---- Wih B-fragments ----
        for (int kc = 0; kc < KC; ++kc)
#pragma unroll
            for (int nt = 0; nt < 2; ++nt) {
                int n  = ns * 16 + nt * 8 + grp;
                int k0 = kc * 16 + 2 * tig;
                float v00 = (k0     < FIN) ? Wih[n * FIN + k0]     : 0.0f;
                float v01 = (k0 + 1 < FIN) ? Wih[n * FIN + k0 + 1] : 0.0f;
                float v10 = (k0 + 8 < FIN) ? Wih[n * FIN + k0 + 8] : 0.0f;
                float v11 = (k0 + 9 < FIN) ? Wih[n * FIN + k0 + 9] : 0.0f;
                __half h0, l0_, h1, l1;
                split16(v00, h0, l0_); split16(v01, h1, l1);
                Bhi[kc][nt][0] = pack2(h0, h1); Blo[kc][nt][0] = pack2(l0_, l1);
                split16(v10, h0, l0_); split16(v11, h1, l1);
                Bhi[kc][nt][1] = pack2(h0, h1); Blo[kc][nt][1] = pack2(l0_, l1);
            }

        float binit[2][2];
#pragma unroll
        for (int nt = 0; nt < 2; ++nt) {
            int c0 = ns * 16 + nt * 8 + 2 * tig;
            binit[nt][0] = bi[c0]     + bh[c0];
            binit[nt][1] = bi[c0 + 1] + bh[c0 + 1];
        }

        // ===================================================================
        // PHASE 1: xp = x @ Wih^T + b
        // ===================================================================
        if (l == 0) {
            __half* AsHh = reinterpret_cast<__half*>(AsH);
            __half* AsLh = reinterpret_cast<__half*>(AsL);
            for (int tp = 0; tp < T; tp += 2) {
                for (int i = tid; i < 2 * 16 * 32; i += NT) {
                    int tt = i >> 9, r = (i >> 5) & 15, k = i & 31;
                    float v = (k < F0)
                        ? x[((size_t)(b0 + r) * T + (tp + tt)) * F0 + k] : 0.0f;
                    __half hi, lo; split16(v, hi, lo);
                    int word = tt * 1024 + (k >> 4) * 128 + awidx(r, k & 15);
                    AsHh[2 * word + (k & 1)] = hi;
                    AsLh[2 * word + (k & 1)] = lo;
                }
                __syncthreads();
#pragma unroll
                for (int tt = 0; tt < 2; ++tt) {
                    float aH[2][4], aL1[2][4], aL2[2][4];
#pragma unroll
                    for (int nt = 0; nt < 2; ++nt)
#pragma unroll
                        for (int j = 0; j < 4; ++j) {
                            aH[nt][j] = binit[nt][j & 1];
                            aL1[nt][j] = 0.0f; aL2[nt][j] = 0.0f;
                        }
#pragma unroll
                    for (int kc = 0; kc < 2; ++kc) {
                        uint4 ah = *(const uint4*)&AsH[tt * 1024 + kc * 128 + lane * 4];
                        uint4 al = *(const uint4*)&AsL[tt * 1024 + kc * 128 + lane * 4];
#pragma unroll
                        for (int nt = 0; nt < 2; ++nt) {
                            mma16(aH[nt],  ah, Bhi[kc][nt]);
                            mma16(aL1[nt], al, Bhi[kc][nt]);
                            mma16(aL2[nt], ah, Blo[kc][nt]);
                        }
                    }
                    float4* dst = (float4*)(xp + (size_t)(tp + tt) * 2048 + ns * 256 + lane * 8);
                    dst[0] = make_float4(aH[0][0] + aL1[0][0] + aL2[0][0],
                                         aH[0][1] + aL1[0][1] + aL2[0][1],
                                         aH[0][2] + aL1[0][2] + aL2[0][2],
                                         aH[0][3] + aL1[0][3] + aL2[0][3]);
                    dst[1] = make_float4(aH[1][0] + aL1[1][0] + aL2[1][0],
                                         aH[1][1] + aL1[1][1] + aL2[1][1],
                                         aH[1][2] + aL1[1][2] + aL2[1][2],
                                         aH[1][3] + aL1[1][3] + aL2[1][3]);
                }
                __syncthreads();
            }
        } else {
            for (int t = 0; t < T; ++t) {
                const uint32_t* pb = act + (size_t)t * 2048;
                float aH[2][4], aL1[2][4], aL2[2][4];
#pragma unroll
                for (int nt = 0; nt < 2; ++nt)
#pragma unroll
                    for (int j = 0; j < 4; ++j) {
                        aH[nt][j] = binit[nt][j & 1];
                        aL1[nt][j] = 0.0f; aL2[nt][j] = 0.0f;
                    }
#pragma unroll
                for (int kc = 0; kc < 8; ++kc) {
                    uint4 ah = *(const uint4*)&pb[kc * 128 + lane * 4];
                    uint4 al = *(const uint4*)&pb[1024 + kc * 128 + lane * 4];
#pragma unroll
                    for (int nt = 0; nt < 2; ++nt) {
                        mma16(aH[nt],  ah, Bhi[kc][nt]);
                        mma16(aL1[nt], al, Bhi[kc][nt]);
                        mma16(aL2[nt], ah, Blo[kc][nt]);
                    }
                }
                float4* dst = (float4*)(xp + (size_t)t * 2048 + ns * 256 + lane * 8);
                dst[0] = make_float4(aH[0][0] + aL1[0][0] + aL2[0][0],
                                     aH[0][1] + aL1[0][1] + aL2[0][1],
                                     aH[0][2] + aL1[0][2] + aL2[0][2],
                                     aH[0][3] + aL1[0][3] + aL2[0][3]);
                dst[1] = make_float4(aH[1][0] + aL1[1][0] + aL2[1][0],
                                     aH[1][1] + aL1[1][1] + aL2[1][1],
                                     aH[1][2] + aL1[1][2] + aL2[1][2],
                                     aH[1][3] + aL1[1][3] + aL2[1][3]);
            }
        }

        // ===================================================================
        // PHASE 2: scan  h = tanh(xp_t + h @ Whh^T)
        // ===================================================================
        const float* Whl = Whh + (size_t)l * H * H;
#pragma unroll
        for (int kc = 0; kc < 8; ++kc)
#pragma unroll
            for (int nt = 0; nt < 2; ++nt) {
                int n  = ns * 16 + nt * 8 + grp;
                int k0 = kc * 16 + 2 * tig;
                __half h0, l0_, h1, l1;
                split16(Whl[n * H + k0],     h0, l0_);
                split16(Whl[n * H + k0 + 1], h1, l1);
                Bhi[kc][nt][0] = pack2(h0, h1); Blo[kc][nt][0] = pack2(l0_, l1);
                split16(Whl[n * H + k0 + 8], h0, l0_);
                split16(Whl[n * H + k0 + 9], h1, l1);
                Bhi[kc][nt][1] = pack2(h0, h1); Blo[kc][nt][1] = pack2(l0_, l1);
            }
        for (int i = tid; i < 1024; i += NT) { AsH[i] = 0u; AsL[i] = 0u; }
        __syncthreads();

        const float4* src0 = (const float4*)(xp + ns * 256 + lane * 8);
        float4 xv0 = src0[0], xv1 = src0[1];
        int p = 0;

        for (int t = 0; t < T; ++t) {
            float aH[2][4], aL1[2][4], aL2[2][4];
            aH[0][0] = xv0.x; aH[0][1] = xv0.y; aH[0][2] = xv0.z; aH[0][3] = xv0.w;
            aH[1][0] = xv1.x; aH[1][1] = xv1.y; aH[1][2] = xv1.z; aH[1][3] = xv1.w;
#pragma unroll
            for (int nt = 0; nt < 2; ++nt)
#pragma unroll
                for (int j = 0; j < 4; ++j) { aL1[nt][j] = 0.0f; aL2[nt][j] = 0.0f; }
            if (t + 1 < T) {
                const float4* nx = (const float4*)(xp + (size_t)(t + 1) * 2048 + ns * 256 + lane * 8);
                xv0 = nx[0]; xv1 = nx[1];
            }
#pragma unroll
            for (int kc = 0; kc < 8; ++kc) {
                uint4 ah = *(const uint4*)&AsH[p * 1024 + kc * 128 + lane * 4];
                uint4 al = *(const uint4*)&AsL[p * 1024 + kc * 128 + lane * 4];
#pragma unroll
                for (int nt = 0; nt < 2; ++nt) {
                    mma16(aH[nt],  ah, Bhi[kc][nt]);
                    mma16(aL1[nt], al, Bhi[kc][nt]);
                    mma16(aL2[nt], ah, Blo[kc][nt]);
                }
            }

            float y[2][4];
#pragma unroll
            for (int nt = 0; nt < 2; ++nt)
#pragma unroll
                for (int j = 0; j < 4; ++j)
                    y[nt][j] = fast_tanh(aH[nt][j] + aL1[nt][j] + aL2[nt][j]);

            uint4 hv, lv;
            {
                __half h0, l0_, h1, l1;
                split16(y[0][0], h0, l0_); split16(y[0][1], h1, l1);
                hv.x = pack2(h0, h1); lv.x = pack2(l0_, l1);
                split16(y[0][2], h0, l0_); split16(y[0][3], h1, l1);
                hv.y = pack2(h0, h1); lv.y = pack2(l0_, l1);
                split16(y[1][0], h0, l0_); split16(y[1][1], h1, l1);
                hv.z = pack2(h0, h1); lv.z = pack2(l0_, l1);
                split16(y[1][2], h0, l0_); split16(y[1][3], h1, l1);
                hv.w = pack2(h0, h1); lv.w = pack2(l0_, l1);
            }
            const int wbase = (1 - p) * 1024 + ns * 128 + lane * 4;
            *(uint4*)&AsH[wbase] = hv;
            *(uint4*)&AsL[wbase] = lv;

            if (l < NL - 1) {
                uint32_t* ob = act + (size_t)t * 2048 + ns * 128 + lane * 4;
                *(uint4*)ob          = hv;
                *(uint4*)(ob + 1024) = lv;
            } else if (t == T - 1) {
#pragma unroll
                for (int nt = 0; nt < 2; ++nt) {
                    int c0 = ns * 16 + nt * 8 + 2 * tig;
                    hsm[grp][c0]         = y[nt][0];
                    hsm[grp][c0 + 1]     = y[nt][1];
                    hsm[grp + 8][c0]     = y[nt][2];
                    hsm[grp + 8][c0 + 1] = y[nt][3];
                }
            }

            __syncthreads();
            p ^= 1;
        }
    }

    // =======================================================================
    // FC head: out[b0+r, c] = hsm[r] . fcW[c] + fcb[c]
    // =======================================================================
    if (tid < BT * NC) {
        int r = tid / NC, c = tid - r * NC;
        const float* wgt = fcW + c * H;
        float s = fcb[c];
#pragma unroll 8
        for (int k = 0; k < H; ++k) s += hsm[r][k] * wgt[k];
        out[(size_t)(b0 + r) * NC + c] = s;
    }
}

extern "C" void kernel_launch(void* const* d_in, const int* in_sizes, int n_in,
                              void* d_out, int out_size)
{
    const float* x    = (const float*)d_in[0];
    const float* Wih0 = (const float*)d_in[1];
    const float* Wih  = (const float*)d_in[2];
    const float* Whh  = (const float*)d_in[3];
    const float* bih  = (const float*)d_in[4];
    const float* bhh  = (const float*)d_in[5];
    const float* fcW  = (const float*)d_in[6];
    const float* fcb  = (const float*)d_in[7];
    float* out = (float*)d_out;

    uint32_t* act;
    float* xps;
    cudaGetSymbolAddress((void**)&act, g_act);
    cudaGetSymbolAddress((void**)&xps, g_xp);

    rnn_net<<<CTAS, NT>>>(x, Wih0, Wih, Whh, bih, bhh, fcW, fcb, out, act, xps);
}

// round 7
// speedup vs baseline: 1.2507x; 1.2507x over previous
#include <cuda_runtime.h>
#include <cuda_fp16.h>
#include <stdint.h>

#define B  4096
#define T  28
#define H  128
#define F0 28
#define NL 10
#define NC 10
#define BT 16           // batch rows per CTA
#define CTAS (B / BT)   // 256
#define NT 512          // 16 warps: 0-7 scan, 8-15 projection

// Static device buffers (no allocation allowed). xp ping-pong, fragment order.
__device__ float g_xpA[(size_t)B * T * H];
__device__ float g_xpB[(size_t)B * T * H];

// ---------------------------------------------------------------------------
// helpers
// ---------------------------------------------------------------------------
__device__ __forceinline__ uint32_t pack2(__half a, __half b) {
    __half2 h = __halves2half2(a, b);
    return *reinterpret_cast<uint32_t*>(&h);
}
__device__ __forceinline__ void split16(float x, __half &hi, __half &lo) {
    hi = __float2half_rn(x);
    lo = __float2half_rn(x - __half2float(hi));
}
__device__ __forceinline__ void mma16(float c[4], uint4 a, const uint32_t b[2]) {
    asm volatile("mma.sync.aligned.m16n8k16.row.col.f32.f16.f16.f32 "
        "{%0,%1,%2,%3}, {%4,%5,%6,%7}, {%8,%9}, {%0,%1,%2,%3};"
        : "+f"(c[0]), "+f"(c[1]), "+f"(c[2]), "+f"(c[3])
        : "r"(a.x), "r"(a.y), "r"(a.z), "r"(a.w), "r"(b[0]), "r"(b[1]));
}
__device__ __forceinline__ float fast_tanh(float x) {
    float e; asm("ex2.approx.f32 %0, %1;" : "=f"(e) : "f"(x * 2.8853900817779268f));
    float r; asm("rcp.approx.f32 %0, %1;" : "=f"(r) : "f"(e + 1.0f));
    return fmaf(-2.0f, r, 1.0f);
}
// A-fragment word index for element (rl 0..15, kk 0..15) of one m16k16 tile
__device__ __forceinline__ int awidx(int rl, int kk) {
    int lane = ((rl & 7) << 2) | ((kk & 7) >> 1);
    int reg  = ((kk & 8) >> 2) | (rl >> 3);
    return lane * 4 + reg;               // half select = kk & 1
}

// ---------------------------------------------------------------------------
// Persistent whole-network kernel with warp specialization:
//   scan warps (0-7):  h_t = tanh(xp_l[t] + h_{t-1} @ Whh_l^T)
//   proj warps (8-15): xp_{l+1}[t-1] = h_{t-1} @ Wih_{l+1}^T + b_{l+1}
// Both read the same double-buffered SMEM h fragments each step.
// ---------------------------------------------------------------------------
__global__ void __launch_bounds__(NT, 1)
rnn_net(const float* __restrict__ x,      // [B, T, F0]
        const float* __restrict__ Wih0,   // [H, F0]
        const float* __restrict__ WihR,   // [NL-1, H, H]
        const float* __restrict__ Whh,    // [NL, H, H]
        const float* __restrict__ bih,    // [NL, H]
        const float* __restrict__ bhh,    // [NL, H]
        const float* __restrict__ fcW,    // [NC, H]
        const float* __restrict__ fcb,    // [NC]
        float*       __restrict__ out,    // [B, NC]
        float*       __restrict__ xpA,
        float*       __restrict__ xpB)
{
    __shared__ __align__(16) uint32_t AsH[2048];   // [2 buf][1024] h hi frags
    __shared__ __align__(16) uint32_t AsL[2048];   // lo frags
    __shared__ float hsm[BT][H];

    const int tid  = threadIdx.x;
    const int lane = tid & 31;
    const int w    = tid >> 5;
    const bool scanw = (w < 8);
    const int ns   = w & 7;              // n-slice for this warp's role
    const int grp  = lane >> 2;
    const int tig  = lane & 3;
    const int b0   = blockIdx.x * BT;
    const size_t cta_off = (size_t)blockIdx.x * (T * 2048);
    float* xp0 = xpA + cta_off;
    float* xp1 = xpB + cta_off;

    // =======================================================================
    // PHASE A: xp0 = x @ Wih0^T + b_0   (all 16 warps; warp parity = t parity)
    // =======================================================================
    {
        uint32_t Phi[2][2][2], Plo[2][2][2];
#pragma unroll
        for (int kc = 0; kc < 2; ++kc)
#pragma unroll
            for (int nt = 0; nt < 2; ++nt) {
                int n  = ns * 16 + nt * 8 + grp;
                int k0 = kc * 16 + 2 * tig;
                float v00 = (k0     < F0) ? Wih0[n * F0 + k0]     : 0.0f;
                float v01 = (k0 + 1 < F0) ? Wih0[n * F0 + k0 + 1] : 0.0f;
                float v10 = (k0 + 8 < F0) ? Wih0[n * F0 + k0 + 8] : 0.0f;
                float v11 = (k0 + 9 < F0) ? Wih0[n * F0 + k0 + 9] : 0.0f;
                __half h0, l0_, h1, l1;
                split16(v00, h0, l0_); split16(v01, h1, l1);
                Phi[kc][nt][0] = pack2(h0, h1); Plo[kc][nt][0] = pack2(l0_, l1);
                split16(v10, h0, l0_); split16(v11, h1, l1);
                Phi[kc][nt][1] = pack2(h0, h1); Plo[kc][nt][1] = pack2(l0_, l1);
            }
        float bi0[2][2];
#pragma unroll
        for (int nt = 0; nt < 2; ++nt) {
            int c0 = ns * 16 + nt * 8 + 2 * tig;
            bi0[nt][0] = bih[c0]     + bhh[c0];
            bi0[nt][1] = bih[c0 + 1] + bhh[c0 + 1];
        }

        __half* AsHh = reinterpret_cast<__half*>(AsH);
        __half* AsLh = reinterpret_cast<__half*>(AsL);
        const int tt = w >> 3;           // which of the two staged timesteps

        for (int tp = 0; tp < T; tp += 2) {
            for (int i = tid; i < 1024; i += NT) {
                int t2 = i >> 9, r = (i >> 5) & 15, k = i & 31;
                float v = (k < F0)
                    ? x[((size_t)(b0 + r) * T + (tp + t2)) * F0 + k] : 0.0f;
                __half hi, lo; split16(v, hi, lo);
                int word = t2 * 1024 + (k >> 4) * 128 + awidx(r, k & 15);
                AsHh[2 * word + (k & 1)] = hi;
                AsLh[2 * word + (k & 1)] = lo;
            }
            __syncthreads();
            {
                float aH[2][4], aL1[2][4], aL2[2][4];
#pragma unroll
                for (int nt = 0; nt < 2; ++nt)
#pragma unroll
                    for (int j = 0; j < 4; ++j) {
                        aH[nt][j] = bi0[nt][j & 1];
                        aL1[nt][j] = 0.0f; aL2[nt][j] = 0.0f;
                    }
#pragma unroll
                for (int kc = 0; kc < 2; ++kc) {
                    uint4 ah = *(const uint4*)&AsH[tt * 1024 + kc * 128 + lane * 4];
                    uint4 al = *(const uint4*)&AsL[tt * 1024 + kc * 128 + lane * 4];
#pragma unroll
                    for (int nt = 0; nt < 2; ++nt) {
                        mma16(aH[nt],  ah, Phi[kc][nt]);
                        mma16(aL1[nt], al, Phi[kc][nt]);
                        mma16(aL2[nt], ah, Plo[kc][nt]);
                    }
                }
                float4* dst = (float4*)(xp0 + (size_t)(tp + tt) * 2048 + ns * 256 + lane * 8);
                dst[0] = make_float4(aH[0][0] + aL1[0][0] + aL2[0][0],
                                     aH[0][1] + aL1[0][1] + aL2[0][1],
                                     aH[0][2] + aL1[0][2] + aL2[0][2],
                                     aH[0][3] + aL1[0][3] + aL2[0][3]);
                dst[1] = make_float4(aH[1][0] + aL1[1][0] + aL2[1][0],
                                     aH[1][1] + aL1[1][1] + aL2[1][1],
                                     aH[1][2] + aL1[1][2] + aL2[1][2],
                                     aH[1][3] + aL1[1][3] + aL2[1][3]);
            }
            __syncthreads();
        }
    }

    // =======================================================================
    // MAIN: 10 fused scan+projection layers
    // =======================================================================
    uint32_t Bhi[8][2][2], Blo[8][2][2];  // role weight fragments
    float bP[2][2];                       // proj bias (layer l+1)

    for (int l = 0; l < NL; ++l) {
        const float* xin  = (l & 1) ? xp1 : xp0;
        float*       xout = (l & 1) ? xp0 : xp1;

        if (scanw) {
            const float* Wl = Whh + (size_t)l * H * H;
#pragma unroll
            for (int kc = 0; kc < 8; ++kc)
#pragma unroll
                for (int nt = 0; nt < 2; ++nt) {
                    int n  = ns * 16 + nt * 8 + grp;
                    int k0 = kc * 16 + 2 * tig;
                    __half h0, l0_, h1, l1;
                    split16(Wl[n * H + k0],     h0, l0_);
                    split16(Wl[n * H + k0 + 1], h1, l1);
                    Bhi[kc][nt][0] = pack2(h0, h1); Blo[kc][nt][0] = pack2(l0_, l1);
                    split16(Wl[n * H + k0 + 8], h0, l0_);
                    split16(Wl[n * H + k0 + 9], h1, l1);
                    Bhi[kc][nt][1] = pack2(h0, h1); Blo[kc][nt][1] = pack2(l0_, l1);
                }
        } else if (l < NL - 1) {
            const float* Wn = WihR + (size_t)l * H * H;   // Wih_{l+1}
#pragma unroll
            for (int kc = 0; kc < 8; ++kc)
#pragma unroll
                for (int nt = 0; nt < 2; ++nt) {
                    int n  = ns * 16 + nt * 8 + grp;
                    int k0 = kc * 16 + 2 * tig;
                    __half h0, l0_, h1, l1;
                    split16(Wn[n * H + k0],     h0, l0_);
                    split16(Wn[n * H + k0 + 1], h1, l1);
                    Bhi[kc][nt][0] = pack2(h0, h1); Blo[kc][nt][0] = pack2(l0_, l1);
                    split16(Wn[n * H + k0 + 8], h0, l0_);
                    split16(Wn[n * H + k0 + 9], h1, l1);
                    Bhi[kc][nt][1] = pack2(h0, h1); Blo[kc][nt][1] = pack2(l0_, l1);
                }
            const float* bi = bih + (size_t)(l + 1) * H;
            const float* bh = bhh + (size_t)(l + 1) * H;
#pragma unroll
            for (int nt = 0; nt < 2; ++nt) {
                int c0 = ns * 16 + nt * 8 + 2 * tig;
                bP[nt][0] = bi[c0]     + bh[c0];
                bP[nt][1] = bi[c0 + 1] + bh[c0 + 1];
            }
        }

        // zero h buffer 0 (h_{-1} = 0)
        for (int i = tid; i < 1024; i += NT) { AsH[i] = 0u; AsL[i] = 0u; }
        __syncthreads();

        int p = 0;
        float4 xv0, xv1;
        if (scanw) {
            const float4* s = (const float4*)(xin + ns * 256 + lane * 8);
            xv0 = s[0]; xv1 = s[1];
        }

        for (int t = 0; t < T; ++t) {
            if (scanw) {
                // ---- scan: h_t from h_{t-1} (buf p) + xp_l[t] ----
                float aH[2][4], aL1[2][4], aL2[2][4];
                aH[0][0] = xv0.x; aH[0][1] = xv0.y; aH[0][2] = xv0.z; aH[0][3] = xv0.w;
                aH[1][0] = xv1.x; aH[1][1] = xv1.y; aH[1][2] = xv1.z; aH[1][3] = xv1.w;
#pragma unroll
                for (int nt = 0; nt < 2; ++nt)
#pragma unroll
                    for (int j = 0; j < 4; ++j) { aL1[nt][j] = 0.0f; aL2[nt][j] = 0.0f; }
                if (t + 1 < T) {
                    const float4* nx = (const float4*)(xin + (size_t)(t + 1) * 2048 + ns * 256 + lane * 8);
                    xv0 = nx[0]; xv1 = nx[1];
                }
#pragma unroll
                for (int kc = 0; kc < 8; ++kc) {
                    uint4 ah = *(const uint4*)&AsH[p * 1024 + kc * 128 + lane * 4];
                    uint4 al = *(const uint4*)&AsL[p * 1024 + kc * 128 + lane * 4];
#pragma unroll
                    for (int nt = 0; nt < 2; ++nt) {
                        mma16(aH[nt],  ah, Bhi[kc][nt]);
                        mma16(aL1[nt], al, Bhi[kc][nt]);
                        mma16(aL2[nt], ah, Blo[kc][nt]);
                    }
                }
                float y[2][4];
#pragma unroll
                for (int nt = 0; nt < 2; ++nt)
#pragma unroll
                    for (int j = 0; j < 4; ++j)
                        y[nt][j] = fast_tanh(aH[nt][j] + aL1[nt][j] + aL2[nt][j]);

                uint4 hv, lv;
                {
                    __half h0, l0_, h1, l1;
                    split16(y[0][0], h0, l0_); split16(y[0][1], h1, l1);
                    hv.x = pack2(h0, h1); lv.x = pack2(l0_, l1);
                    split16(y[0][2], h0, l0_); split16(y[0][3], h1, l1);
                    hv.y = pack2(h0, h1); lv.y = pack2(l0_, l1);
                    split16(y[1][0], h0, l0_); split16(y[1][1], h1, l1);
                    hv.z = pack2(h0, h1); lv.z = pack2(l0_, l1);
                    split16(y[1][2], h0, l0_); split16(y[1][3], h1, l1);
                    hv.w = pack2(h0, h1); lv.w = pack2(l0_, l1);
                }
                const int wbase = (1 - p) * 1024 + ns * 128 + lane * 4;
                *(uint4*)&AsH[wbase] = hv;
                *(uint4*)&AsL[wbase] = lv;

                if (l == NL - 1 && t == T - 1) {
#pragma unroll
                    for (int nt = 0; nt < 2; ++nt) {
                        int c0 = ns * 16 + nt * 8 + 2 * tig;
                        hsm[grp][c0]         = y[nt][0];
                        hsm[grp][c0 + 1]     = y[nt][1];
                        hsm[grp + 8][c0]     = y[nt][2];
                        hsm[grp + 8][c0 + 1] = y[nt][3];
                    }
                }
            } else if (l < NL - 1 && t > 0) {
                // ---- proj: xp_{l+1}[t-1] = h_{t-1}(buf p) @ Wih_{l+1}^T + b ----
                float pH[2][4], pL1[2][4], pL2[2][4];
#pragma unroll
                for (int nt = 0; nt < 2; ++nt)
#pragma unroll
                    for (int j = 0; j < 4; ++j) {
                        pH[nt][j] = bP[nt][j & 1];
                        pL1[nt][j] = 0.0f; pL2[nt][j] = 0.0f;
                    }
#pragma unroll
                for (int kc = 0; kc < 8; ++kc) {
                    uint4 ah = *(const uint4*)&AsH[p * 1024 + kc * 128 + lane * 4];
                    uint4 al = *(const uint4*)&AsL[p * 1024 + kc * 128 + lane * 4];
#pragma unroll
                    for (int nt = 0; nt < 2; ++nt) {
                        mma16(pH[nt],  ah, Bhi[kc][nt]);
                        mma16(pL1[nt], al, Bhi[kc][nt]);
                        mma16(pL2[nt], ah, Blo[kc][nt]);
                    }
                }
                float4* dst = (float4*)(xout + (size_t)(t - 1) * 2048 + ns * 256 + lane * 8);
                dst[0] = make_float4(pH[0][0] + pL1[0][0] + pL2[0][0],
                                     pH[0][1] + pL1[0][1] + pL2[0][1],
                                     pH[0][2] + pL1[0][2] + pL2[0][2],
                                     pH[0][3] + pL1[0][3] + pL2[0][3]);
                dst[1] = make_float4(pH[1][0] + pL1[1][0] + pL2[1][0],
                                     pH[1][1] + pL1[1][1] + pL2[1][1],
                                     pH[1][2] + pL1[1][2] + pL2[1][2],
                                     pH[1][3] + pL1[1][3] + pL2[1][3]);
            }
            __syncthreads();
            p ^= 1;
        }

        // tail: project h_{T-1} (in buf p after even T flips)
        if (!scanw && l < NL - 1) {
            float pH[2][4], pL1[2][4], pL2[2][4];
#pragma unroll
            for (int nt = 0; nt < 2; ++nt)
#pragma unroll
                for (int j = 0; j < 4; ++j) {
                    pH[nt][j] = bP[nt][j & 1];
                    pL1[nt][j] = 0.0f; pL2[nt][j] = 0.0f;
                }
#pragma unroll
            for (int kc = 0; kc < 8; ++kc) {
                uint4 ah = *(const uint4*)&AsH[p * 1024 + kc * 128 + lane * 4];
                uint4 al = *(const uint4*)&AsL[p * 1024 + kc * 128 + lane * 4];
#pragma unroll
                for (int nt = 0; nt < 2; ++nt) {
                    mma16(pH[nt],  ah, Bhi[kc][nt]);
                    mma16(pL1[nt], al, Bhi[kc][nt]);
                    mma16(pL2[nt], ah, Blo[kc][nt]);
                }
            }
            float4* dst = (float4*)(xout + (size_t)(T - 1) * 2048 + ns * 256 + lane * 8);
            dst[0] = make_float4(pH[0][0] + pL1[0][0] + pL2[0][0],
                                 pH[0][1] + pL1[0][1] + pL2[0][1],
                                 pH[0][2] + pL1[0][2] + pL2[0][2],
                                 pH[0][3] + pL1[0][3] + pL2[0][3]);
            dst[1] = make_float4(pH[1][0] + pL1[1][0] + pL2[1][0],
                                 pH[1][1] + pL1[1][1] + pL2[1][1],
                                 pH[1][2] + pL1[1][2] + pL2[1][2],
                                 pH[1][3] + pL1[1][3] + pL2[1][3]);
        }
        __syncthreads();
    }

    // =======================================================================
    // FC head
    // =======================================================================
    if (tid < BT * NC) {
        int r = tid / NC, c = tid - r * NC;
        const float* wgt = fcW + c * H;
        float s = fcb[c];
#pragma unroll 8
        for (int k = 0; k < H; ++k) s += hsm[r][k] * wgt[k];
        out[(size_t)(b0 + r) * NC + c] = s;
    }
}

extern "C" void kernel_launch(void* const* d_in, const int* in_sizes, int n_in,
                              void* d_out, int out_size)
{
    const float* x    = (const float*)d_in[0];
    const float* Wih0 = (const float*)d_in[1];
    const float* Wih  = (const float*)d_in[2];
    const float* Whh  = (const float*)d_in[3];
    const float* bih  = (const float*)d_in[4];
    const float* bhh  = (const float*)d_in[5];
    const float* fcW  = (const float*)d_in[6];
    const float* fcb  = (const float*)d_in[7];
    float* out = (float*)d_out;

    float *xpA, *xpB;
    cudaGetSymbolAddress((void**)&xpA, g_xpA);
    cudaGetSymbolAddress((void**)&xpB, g_xpB);

    rnn_net<<<CTAS, NT>>>(x, Wih0, Wih, Whh, bih, bhh, fcW, fcb, out, xpA, xpB);
}

// round 8
// speedup vs baseline: 1.6383x; 1.3099x over previous
#include <cuda_runtime.h>
#include <cuda_fp16.h>
#include <stdint.h>

#define B  4096
#define T  28
#define H  128
#define F0 28
#define NL 10
#define NC 10
#define BT 16           // batch rows per CTA
#define CTAS (B / BT)   // 256
#define NT 512          // 16 warps: 0-7 scan, 8-15 projection

// Static device buffers (no allocation allowed). xp ping-pong, fragment order.
__device__ float g_xpA[(size_t)B * T * H];
__device__ float g_xpB[(size_t)B * T * H];

// ---------------------------------------------------------------------------
// helpers
// ---------------------------------------------------------------------------
__device__ __forceinline__ uint32_t pack2(__half a, __half b) {
    __half2 h = __halves2half2(a, b);
    return *reinterpret_cast<uint32_t*>(&h);
}
__device__ __forceinline__ void split16(float x, __half &hi, __half &lo) {
    hi = __float2half_rn(x);
    lo = __float2half_rn(x - __half2float(hi));
}
__device__ __forceinline__ void mma16(float c[4], uint4 a, const uint32_t b[2]) {
    asm volatile("mma.sync.aligned.m16n8k16.row.col.f32.f16.f16.f32 "
        "{%0,%1,%2,%3}, {%4,%5,%6,%7}, {%8,%9}, {%0,%1,%2,%3};"
        : "+f"(c[0]), "+f"(c[1]), "+f"(c[2]), "+f"(c[3])
        : "r"(a.x), "r"(a.y), "r"(a.z), "r"(a.w), "r"(b[0]), "r"(b[1]));
}
__device__ __forceinline__ float fast_tanh(float x) {
    float e; asm("ex2.approx.f32 %0, %1;" : "=f"(e) : "f"(x * 2.8853900817779268f));
    float r; asm("rcp.approx.f32 %0, %1;" : "=f"(r) : "f"(e + 1.0f));
    return fmaf(-2.0f, r, 1.0f);
}
// A-fragment word index for element (rl 0..15, kk 0..15) of one m16k16 tile
__device__ __forceinline__ int awidx(int rl, int kk) {
    int lane = ((rl & 7) << 2) | ((kk & 7) >> 1);
    int reg  = ((kk & 8) >> 2) | (rl >> 3);
    return lane * 4 + reg;               // half select = kk & 1
}

// ---------------------------------------------------------------------------
// Persistent whole-network kernel, warp-specialized:
//   scan warps (0-7):  h_t = tanh(xp_l[t] + h_{t-1} @ Whh_l^T)
//   proj warps (8-15): xp_{l+1}[t-1] = h_{t-1} @ Wih_{l+1}^T + b_{l+1}
// Split-2 arithmetic: activations single fp16 (Ah); weights exact hi+lo
// fp16 pair (Bh,Bl):  C = Ah*Bh + Ah*Bl.
// ---------------------------------------------------------------------------
__global__ void __launch_bounds__(NT, 1)
rnn_net(const float* __restrict__ x,      // [B, T, F0]
        const float* __restrict__ Wih0,   // [H, F0]
        const float* __restrict__ WihR,   // [NL-1, H, H]
        const float* __restrict__ Whh,    // [NL, H, H]
        const float* __restrict__ bih,    // [NL, H]
        const float* __restrict__ bhh,    // [NL, H]
        const float* __restrict__ fcW,    // [NC, H]
        const float* __restrict__ fcb,    // [NC]
        float*       __restrict__ out,    // [B, NC]
        float*       __restrict__ xpA,
        float*       __restrict__ xpB)
{
    __shared__ __align__(16) uint32_t AsH[2048];   // [2 buf][1024] h fragments
    __shared__ float hsm[BT][H];

    const int tid  = threadIdx.x;
    const int lane = tid & 31;
    const int w    = tid >> 5;
    const bool scanw = (w < 8);
    const int ns   = w & 7;
    const int grp  = lane >> 2;
    const int tig  = lane & 3;
    const int b0   = blockIdx.x * BT;
    const size_t cta_off = (size_t)blockIdx.x * (T * 2048);
    float* xp0 = xpA + cta_off;
    float* xp1 = xpB + cta_off;

    // =======================================================================
    // PHASE A: xp0 = x @ Wih0^T + b_0   (all 16 warps; warp group = t parity)
    // =======================================================================
    {
        uint32_t Phi[2][2][2], Plo[2][2][2];
#pragma unroll
        for (int kc = 0; kc < 2; ++kc)
#pragma unroll
            for (int nt = 0; nt < 2; ++nt) {
                int n  = ns * 16 + nt * 8 + grp;
                int k0 = kc * 16 + 2 * tig;
                float v00 = (k0     < F0) ? Wih0[n * F0 + k0]     : 0.0f;
                float v01 = (k0 + 1 < F0) ? Wih0[n * F0 + k0 + 1] : 0.0f;
                float v10 = (k0 + 8 < F0) ? Wih0[n * F0 + k0 + 8] : 0.0f;
                float v11 = (k0 + 9 < F0) ? Wih0[n * F0 + k0 + 9] : 0.0f;
                __half h0, l0_, h1, l1;
                split16(v00, h0, l0_); split16(v01, h1, l1);
                Phi[kc][nt][0] = pack2(h0, h1); Plo[kc][nt][0] = pack2(l0_, l1);
                split16(v10, h0, l0_); split16(v11, h1, l1);
                Phi[kc][nt][1] = pack2(h0, h1); Plo[kc][nt][1] = pack2(l0_, l1);
            }
        float bi0[2][2];
#pragma unroll
        for (int nt = 0; nt < 2; ++nt) {
            int c0 = ns * 16 + nt * 8 + 2 * tig;
            bi0[nt][0] = bih[c0]     + bhh[c0];
            bi0[nt][1] = bih[c0 + 1] + bhh[c0 + 1];
        }

        __half* AsHh = reinterpret_cast<__half*>(AsH);
        const int tt = w >> 3;           // which of the two staged timesteps

        for (int tp = 0; tp < T; tp += 2) {
            for (int i = tid; i < 1024; i += NT) {
                int t2 = i >> 9, r = (i >> 5) & 15, k = i & 31;
                float v = (k < F0)
                    ? x[((size_t)(b0 + r) * T + (tp + t2)) * F0 + k] : 0.0f;
                int word = t2 * 1024 + (k >> 4) * 128 + awidx(r, k & 15);
                AsHh[2 * word + (k & 1)] = __float2half_rn(v);
            }
            __syncthreads();
            {
                float aH[2][4], aL[2][4];
#pragma unroll
                for (int nt = 0; nt < 2; ++nt)
#pragma unroll
                    for (int j = 0; j < 4; ++j) {
                        aH[nt][j] = bi0[nt][j & 1];
                        aL[nt][j] = 0.0f;
                    }
#pragma unroll
                for (int kc = 0; kc < 2; ++kc) {
                    uint4 ah = *(const uint4*)&AsH[tt * 1024 + kc * 128 + lane * 4];
#pragma unroll
                    for (int nt = 0; nt < 2; ++nt) {
                        mma16(aH[nt], ah, Phi[kc][nt]);
                        mma16(aL[nt], ah, Plo[kc][nt]);
                    }
                }
                float4* dst = (float4*)(xp0 + (size_t)(tp + tt) * 2048 + ns * 256 + lane * 8);
                dst[0] = make_float4(aH[0][0] + aL[0][0], aH[0][1] + aL[0][1],
                                     aH[0][2] + aL[0][2], aH[0][3] + aL[0][3]);
                dst[1] = make_float4(aH[1][0] + aL[1][0], aH[1][1] + aL[1][1],
                                     aH[1][2] + aL[1][2], aH[1][3] + aL[1][3]);
            }
            __syncthreads();
        }
    }

    // =======================================================================
    // MAIN: 10 fused scan+projection layers
    // =======================================================================
    uint32_t Bhi[8][2][2], Blo[8][2][2];  // role weight fragments (hi+lo)
    float bP[2][2];                       // proj bias (layer l+1)

    for (int l = 0; l < NL; ++l) {
        const float* xin  = (l & 1) ? xp1 : xp0;
        float*       xout = (l & 1) ? xp0 : xp1;

        if (scanw) {
            const float* Wl = Whh + (size_t)l * H * H;
#pragma unroll
            for (int kc = 0; kc < 8; ++kc)
#pragma unroll
                for (int nt = 0; nt < 2; ++nt) {
                    int n  = ns * 16 + nt * 8 + grp;
                    int k0 = kc * 16 + 2 * tig;
                    __half h0, l0_, h1, l1;
                    split16(Wl[n * H + k0],     h0, l0_);
                    split16(Wl[n * H + k0 + 1], h1, l1);
                    Bhi[kc][nt][0] = pack2(h0, h1); Blo[kc][nt][0] = pack2(l0_, l1);
                    split16(Wl[n * H + k0 + 8], h0, l0_);
                    split16(Wl[n * H + k0 + 9], h1, l1);
                    Bhi[kc][nt][1] = pack2(h0, h1); Blo[kc][nt][1] = pack2(l0_, l1);
                }
        } else if (l < NL - 1) {
            const float* Wn = WihR + (size_t)l * H * H;   // Wih_{l+1}
#pragma unroll
            for (int kc = 0; kc < 8; ++kc)
#pragma unroll
                for (int nt = 0; nt < 2; ++nt) {
                    int n  = ns * 16 + nt * 8 + grp;
                    int k0 = kc * 16 + 2 * tig;
                    __half h0, l0_, h1, l1;
                    split16(Wn[n * H + k0],     h0, l0_);
                    split16(Wn[n * H + k0 + 1], h1, l1);
                    Bhi[kc][nt][0] = pack2(h0, h1); Blo[kc][nt][0] = pack2(l0_, l1);
                    split16(Wn[n * H + k0 + 8], h0, l0_);
                    split16(Wn[n * H + k0 + 9], h1, l1);
                    Bhi[kc][nt][1] = pack2(h0, h1); Blo[kc][nt][1] = pack2(l0_, l1);
                }
            const float* bi = bih + (size_t)(l + 1) * H;
            const float* bh = bhh + (size_t)(l + 1) * H;
#pragma unroll
            for (int nt = 0; nt < 2; ++nt) {
                int c0 = ns * 16 + nt * 8 + 2 * tig;
                bP[nt][0] = bi[c0]     + bh[c0];
                bP[nt][1] = bi[c0 + 1] + bh[c0 + 1];
            }
        }

        // zero h buffer 0 (h_{-1} = 0)
        for (int i = tid; i < 1024; i += NT) AsH[i] = 0u;
        __syncthreads();

        int p = 0;
        float4 xv0, xv1;
        if (scanw) {
            const float4* s = (const float4*)(xin + ns * 256 + lane * 8);
            xv0 = s[0]; xv1 = s[1];
        }

        for (int t = 0; t < T; ++t) {
            if (scanw) {
                // ---- scan: h_t from h_{t-1} (buf p) + xp_l[t] ----
                float aH[2][4], aL[2][4];
                aH[0][0] = xv0.x; aH[0][1] = xv0.y; aH[0][2] = xv0.z; aH[0][3] = xv0.w;
                aH[1][0] = xv1.x; aH[1][1] = xv1.y; aH[1][2] = xv1.z; aH[1][3] = xv1.w;
#pragma unroll
                for (int nt = 0; nt < 2; ++nt)
#pragma unroll
                    for (int j = 0; j < 4; ++j) aL[nt][j] = 0.0f;
                if (t + 1 < T) {
                    const float4* nx = (const float4*)(xin + (size_t)(t + 1) * 2048 + ns * 256 + lane * 8);
                    xv0 = nx[0]; xv1 = nx[1];
                }
#pragma unroll
                for (int kc = 0; kc < 8; ++kc) {
                    uint4 ah = *(const uint4*)&AsH[p * 1024 + kc * 128 + lane * 4];
#pragma unroll
                    for (int nt = 0; nt < 2; ++nt) {
                        mma16(aH[nt], ah, Bhi[kc][nt]);
                        mma16(aL[nt], ah, Blo[kc][nt]);
                    }
                }
                float y[2][4];
#pragma unroll
                for (int nt = 0; nt < 2; ++nt)
#pragma unroll
                    for (int j = 0; j < 4; ++j)
                        y[nt][j] = fast_tanh(aH[nt][j] + aL[nt][j]);

                uint4 hv;
                hv.x = pack2(__float2half_rn(y[0][0]), __float2half_rn(y[0][1]));
                hv.y = pack2(__float2half_rn(y[0][2]), __float2half_rn(y[0][3]));
                hv.z = pack2(__float2half_rn(y[1][0]), __float2half_rn(y[1][1]));
                hv.w = pack2(__float2half_rn(y[1][2]), __float2half_rn(y[1][3]));
                *(uint4*)&AsH[(1 - p) * 1024 + ns * 128 + lane * 4] = hv;

                if (l == NL - 1 && t == T - 1) {
#pragma unroll
                    for (int nt = 0; nt < 2; ++nt) {
                        int c0 = ns * 16 + nt * 8 + 2 * tig;
                        hsm[grp][c0]         = y[nt][0];
                        hsm[grp][c0 + 1]     = y[nt][1];
                        hsm[grp + 8][c0]     = y[nt][2];
                        hsm[grp + 8][c0 + 1] = y[nt][3];
                    }
                }
            } else if (l < NL - 1 && t > 0) {
                // ---- proj: xp_{l+1}[t-1] = h_{t-1}(buf p) @ Wih_{l+1}^T + b ----
                float pH[2][4], pL[2][4];
#pragma unroll
                for (int nt = 0; nt < 2; ++nt)
#pragma unroll
                    for (int j = 0; j < 4; ++j) {
                        pH[nt][j] = bP[nt][j & 1];
                        pL[nt][j] = 0.0f;
                    }
#pragma unroll
                for (int kc = 0; kc < 8; ++kc) {
                    uint4 ah = *(const uint4*)&AsH[p * 1024 + kc * 128 + lane * 4];
#pragma unroll
                    for (int nt = 0; nt < 2; ++nt) {
                        mma16(pH[nt], ah, Bhi[kc][nt]);
                        mma16(pL[nt], ah, Blo[kc][nt]);
                    }
                }
                float4* dst = (float4*)(xout + (size_t)(t - 1) * 2048 + ns * 256 + lane * 8);
                dst[0] = make_float4(pH[0][0] + pL[0][0], pH[0][1] + pL[0][1],
                                     pH[0][2] + pL[0][2], pH[0][3] + pL[0][3]);
                dst[1] = make_float4(pH[1][0] + pL[1][0], pH[1][1] + pL[1][1],
                                     pH[1][2] + pL[1][2], pH[1][3] + pL[1][3]);
            }
            __syncthreads();
            p ^= 1;
        }

        // tail: project h_{T-1} (in buf p)
        if (!scanw && l < NL - 1) {
            float pH[2][4], pL[2][4];
#pragma unroll
            for (int nt = 0; nt < 2; ++nt)
#pragma unroll
                for (int j = 0; j < 4; ++j) {
                    pH[nt][j] = bP[nt][j & 1];
                    pL[nt][j] = 0.0f;
                }
#pragma unroll
            for (int kc = 0; kc < 8; ++kc) {
                uint4 ah = *(const uint4*)&AsH[p * 1024 + kc * 128 + lane * 4];
#pragma unroll
                for (int nt = 0; nt < 2; ++nt) {
                    mma16(pH[nt], ah, Bhi[kc][nt]);
                    mma16(pL[nt], ah, Blo[kc][nt]);
                }
            }
            float4* dst = (float4*)(xout + (size_t)(T - 1) * 2048 + ns * 256 + lane * 8);
            dst[0] = make_float4(pH[0][0] + pL[0][0], pH[0][1] + pL[0][1],
                                 pH[0][2] + pL[0][2], pH[0][3] + pL[0][3]);
            dst[1] = make_float4(pH[1][0] + pL[1][0], pH[1][1] + pL[1][1],
                                 pH[1][2] + pL[1][2], pH[1][3] + pL[1][3]);
        }
        __syncthreads();
    }

    // =======================================================================
    // FC head
    // =======================================================================
    if (tid < BT * NC) {
        int r = tid / NC, c = tid - r * NC;
        const float* wgt = fcW + c * H;
        float s = fcb[c];
#pragma unroll 8
        for (int k = 0; k < H; ++k) s += hsm[r][k] * wgt[k];
        out[(size_t)(b0 + r) * NC + c] = s;
    }
}

extern "C" void kernel_launch(void* const* d_in, const int* in_sizes, int n_in,
                              void* d_out, int out_size)
{
    const float* x    = (const float*)d_in[0];
    const float* Wih0 = (const float*)d_in[1];
    const float* Wih  = (const float*)d_in[2];
    const float* Whh  = (const float*)d_in[3];
    const float* bih  = (const float*)d_in[4];
    const float* bhh  = (const float*)d_in[5];
    const float* fcW  = (const float*)d_in[6];
    const float* fcb  = (const float*)d_in[7];
    float* out = (float*)d_out;

    float *xpA, *xpB;
    cudaGetSymbolAddress((void**)&xpA, g_xpA);
    cudaGetSymbolAddress((void**)&xpB, g_xpB);

    rnn_net<<<CTAS, NT>>>(x, Wih0, Wih, Whh, bih, bhh, fcW, fcb, out, xpA, xpB);
}

// round 9
// speedup vs baseline: 2.0442x; 1.2478x over previous
#include <cuda_runtime.h>
#include <cuda_fp16.h>
#include <stdint.h>

#define B  4096
#define T  28
#define H  128
#define F0 28
#define NL 10
#define NC 10
#define BT 32           // batch rows per CTA (two m16 tiles)
#define CTAS (B / BT)   // 128 -> single wave on 148 SMs
#define NT 512          // 16 warps: 0-7 scan, 8-15 projection

// Static device buffers (no allocation allowed). xp ping-pong, fragment order.
__device__ float g_xpA[(size_t)B * T * H];
__device__ float g_xpB[(size_t)B * T * H];

// ---------------------------------------------------------------------------
// helpers
// ---------------------------------------------------------------------------
__device__ __forceinline__ uint32_t pack2(__half a, __half b) {
    __half2 h = __halves2half2(a, b);
    return *reinterpret_cast<uint32_t*>(&h);
}
__device__ __forceinline__ void split16(float x, __half &hi, __half &lo) {
    hi = __float2half_rn(x);
    lo = __float2half_rn(x - __half2float(hi));
}
__device__ __forceinline__ void mma16(float c[4], uint4 a, const uint32_t b[2]) {
    asm volatile("mma.sync.aligned.m16n8k16.row.col.f32.f16.f16.f32 "
        "{%0,%1,%2,%3}, {%4,%5,%6,%7}, {%8,%9}, {%0,%1,%2,%3};"
        : "+f"(c[0]), "+f"(c[1]), "+f"(c[2]), "+f"(c[3])
        : "r"(a.x), "r"(a.y), "r"(a.z), "r"(a.w), "r"(b[0]), "r"(b[1]));
}
__device__ __forceinline__ float fast_tanh(float x) {
    float e; asm("ex2.approx.f32 %0, %1;" : "=f"(e) : "f"(x * 2.8853900817779268f));
    float r; asm("rcp.approx.f32 %0, %1;" : "=f"(r) : "f"(e + 1.0f));
    return fmaf(-2.0f, r, 1.0f);
}
// A-fragment word index for element (rl 0..15, kk 0..15) of one m16k16 tile
__device__ __forceinline__ int awidx(int rl, int kk) {
    int lane = ((rl & 7) << 2) | ((kk & 7) >> 1);
    int reg  = ((kk & 8) >> 2) | (rl >> 3);
    return lane * 4 + reg;               // half select = kk & 1
}

// ---------------------------------------------------------------------------
// Persistent whole-network kernel, warp-specialized, 2 m-tiles per warp:
//   scan warps (0-7):  h_t = tanh(xp_l[t] + h_{t-1} @ Whh_l^T)
//   proj warps (8-15): xp_{l+1}[t-1] = h_{t-1} @ Wih_{l+1}^T + b_{l+1}
// Split-2: activations fp16, weights exact fp16 hi+lo, merged accumulator.
// ---------------------------------------------------------------------------
__global__ void __launch_bounds__(NT, 1)
rnn_net(const float* __restrict__ x,      // [B, T, F0]
        const float* __restrict__ Wih0,   // [H, F0]
        const float* __restrict__ WihR,   // [NL-1, H, H]
        const float* __restrict__ Whh,    // [NL, H, H]
        const float* __restrict__ bih,    // [NL, H]
        const float* __restrict__ bhh,    // [NL, H]
        const float* __restrict__ fcW,    // [NC, H]
        const float* __restrict__ fcb,    // [NC]
        float*       __restrict__ out,    // [B, NC]
        float*       __restrict__ xpA,
        float*       __restrict__ xpB)
{
    // h fragments: [buf][m2][kc][lane*4+reg]  (2*2*1024 words)
    __shared__ __align__(16) uint32_t AsH[4096];
    __shared__ float hsm[BT][H];

    const int tid  = threadIdx.x;
    const int lane = tid & 31;
    const int w    = tid >> 5;
    const bool scanw = (w < 8);
    const int ns   = w & 7;
    const int grp  = lane >> 2;
    const int tig  = lane & 3;
    const int b0   = blockIdx.x * BT;
    const size_t cta_off = (size_t)blockIdx.x * (T * 4096);
    float* xp0 = xpA + cta_off;
    float* xp1 = xpB + cta_off;

    // =======================================================================
    // PHASE A: xp0 = x @ Wih0^T + b_0.  Warp w -> tile (m2 = w>>3, ns).
    // =======================================================================
    {
        const int am2 = w >> 3;
        uint32_t Phi[2][2][2], Plo[2][2][2];
#pragma unroll
        for (int kc = 0; kc < 2; ++kc)
#pragma unroll
            for (int nt = 0; nt < 2; ++nt) {
                int n  = ns * 16 + nt * 8 + grp;
                int k0 = kc * 16 + 2 * tig;
                float v00 = (k0     < F0) ? Wih0[n * F0 + k0]     : 0.0f;
                float v01 = (k0 + 1 < F0) ? Wih0[n * F0 + k0 + 1] : 0.0f;
                float v10 = (k0 + 8 < F0) ? Wih0[n * F0 + k0 + 8] : 0.0f;
                float v11 = (k0 + 9 < F0) ? Wih0[n * F0 + k0 + 9] : 0.0f;
                __half h0, l0_, h1, l1;
                split16(v00, h0, l0_); split16(v01, h1, l1);
                Phi[kc][nt][0] = pack2(h0, h1); Plo[kc][nt][0] = pack2(l0_, l1);
                split16(v10, h0, l0_); split16(v11, h1, l1);
                Phi[kc][nt][1] = pack2(h0, h1); Plo[kc][nt][1] = pack2(l0_, l1);
            }
        float bi0[2][2];
#pragma unroll
        for (int nt = 0; nt < 2; ++nt) {
            int c0 = ns * 16 + nt * 8 + 2 * tig;
            bi0[nt][0] = bih[c0]     + bhh[c0];
            bi0[nt][1] = bih[c0 + 1] + bhh[c0 + 1];
        }

        __half* AsHh = reinterpret_cast<__half*>(AsH);
        for (int t = 0; t < T; ++t) {
            for (int i = tid; i < 1024; i += NT) {
                int r = i >> 5, k = i & 31;
                float v = (k < F0)
                    ? x[((size_t)(b0 + r) * T + t) * F0 + k] : 0.0f;
                int word = (r >> 4) * 1024 + (k >> 4) * 128 + awidx(r & 15, k & 15);
                AsHh[2 * word + (k & 1)] = __float2half_rn(v);
            }
            __syncthreads();
            {
                float acc[2][4];
#pragma unroll
                for (int nt = 0; nt < 2; ++nt)
#pragma unroll
                    for (int j = 0; j < 4; ++j) acc[nt][j] = bi0[nt][j & 1];
#pragma unroll
                for (int kc = 0; kc < 2; ++kc) {
                    uint4 ah = *(const uint4*)&AsH[am2 * 1024 + kc * 128 + lane * 4];
#pragma unroll
                    for (int nt = 0; nt < 2; ++nt) {
                        mma16(acc[nt], ah, Phi[kc][nt]);
                        mma16(acc[nt], ah, Plo[kc][nt]);
                    }
                }
                float4* dst = (float4*)(xp0 + (size_t)t * 4096 + am2 * 2048 + ns * 256 + lane * 8);
                dst[0] = make_float4(acc[0][0], acc[0][1], acc[0][2], acc[0][3]);
                dst[1] = make_float4(acc[1][0], acc[1][1], acc[1][2], acc[1][3]);
            }
            __syncthreads();
        }
    }

    // =======================================================================
    // MAIN: 10 fused scan+projection layers
    // =======================================================================
    uint32_t Bhi[8][2][2], Blo[8][2][2];  // role weight fragments (hi+lo)
    float bP[2][2];                       // proj bias (layer l+1)

    for (int l = 0; l < NL; ++l) {
        const float* xin  = (l & 1) ? xp1 : xp0;
        float*       xout = (l & 1) ? xp0 : xp1;

        {
            const float* Wsel = scanw ? (Whh + (size_t)l * H * H)
                                      : (l < NL - 1 ? WihR + (size_t)l * H * H : nullptr);
            if (Wsel) {
#pragma unroll
                for (int kc = 0; kc < 8; ++kc)
#pragma unroll
                    for (int nt = 0; nt < 2; ++nt) {
                        int n  = ns * 16 + nt * 8 + grp;
                        int k0 = kc * 16 + 2 * tig;
                        __half h0, l0_, h1, l1;
                        split16(Wsel[n * H + k0],     h0, l0_);
                        split16(Wsel[n * H + k0 + 1], h1, l1);
                        Bhi[kc][nt][0] = pack2(h0, h1); Blo[kc][nt][0] = pack2(l0_, l1);
                        split16(Wsel[n * H + k0 + 8], h0, l0_);
                        split16(Wsel[n * H + k0 + 9], h1, l1);
                        Bhi[kc][nt][1] = pack2(h0, h1); Blo[kc][nt][1] = pack2(l0_, l1);
                    }
            }
            if (!scanw && l < NL - 1) {
                const float* bi = bih + (size_t)(l + 1) * H;
                const float* bh = bhh + (size_t)(l + 1) * H;
#pragma unroll
                for (int nt = 0; nt < 2; ++nt) {
                    int c0 = ns * 16 + nt * 8 + 2 * tig;
                    bP[nt][0] = bi[c0]     + bh[c0];
                    bP[nt][1] = bi[c0 + 1] + bh[c0 + 1];
                }
            }
        }

        // zero h buffer 0 (h_{-1} = 0)
        for (int i = tid; i < 2048; i += NT) AsH[i] = 0u;
        __syncthreads();

        int p = 0;
        float4 xv00, xv01, xv10, xv11;
        if (scanw) {
            const float4* s0 = (const float4*)(xin + ns * 256 + lane * 8);
            const float4* s1 = (const float4*)(xin + 2048 + ns * 256 + lane * 8);
            xv00 = s0[0]; xv01 = s0[1]; xv10 = s1[0]; xv11 = s1[1];
        }

        for (int t = 0; t < T; ++t) {
            if (scanw) {
                // ---- scan: h_t = tanh(xp[t] + h_{t-1} @ Whh^T), 2 m-tiles ----
                float acc[2][2][4];     // [m2][nt][4]
                acc[0][0][0] = xv00.x; acc[0][0][1] = xv00.y; acc[0][0][2] = xv00.z; acc[0][0][3] = xv00.w;
                acc[0][1][0] = xv01.x; acc[0][1][1] = xv01.y; acc[0][1][2] = xv01.z; acc[0][1][3] = xv01.w;
                acc[1][0][0] = xv10.x; acc[1][0][1] = xv10.y; acc[1][0][2] = xv10.z; acc[1][0][3] = xv10.w;
                acc[1][1][0] = xv11.x; acc[1][1][1] = xv11.y; acc[1][1][2] = xv11.z; acc[1][1][3] = xv11.w;
                if (t + 1 < T) {
                    const float4* n0 = (const float4*)(xin + (size_t)(t + 1) * 4096 + ns * 256 + lane * 8);
                    const float4* n1 = (const float4*)(xin + (size_t)(t + 1) * 4096 + 2048 + ns * 256 + lane * 8);
                    xv00 = n0[0]; xv01 = n0[1]; xv10 = n1[0]; xv11 = n1[1];
                }
#pragma unroll
                for (int kc = 0; kc < 8; ++kc) {
                    uint4 a0 = *(const uint4*)&AsH[p * 2048 + kc * 128 + lane * 4];
                    uint4 a1 = *(const uint4*)&AsH[p * 2048 + 1024 + kc * 128 + lane * 4];
#pragma unroll
                    for (int nt = 0; nt < 2; ++nt) {
                        mma16(acc[0][nt], a0, Bhi[kc][nt]);
                        mma16(acc[0][nt], a0, Blo[kc][nt]);
                        mma16(acc[1][nt], a1, Bhi[kc][nt]);
                        mma16(acc[1][nt], a1, Blo[kc][nt]);
                    }
                }
#pragma unroll
                for (int m2 = 0; m2 < 2; ++m2) {
                    float y[2][4];
#pragma unroll
                    for (int nt = 0; nt < 2; ++nt)
#pragma unroll
                        for (int j = 0; j < 4; ++j)
                            y[nt][j] = fast_tanh(acc[m2][nt][j]);
                    uint4 hv;
                    hv.x = pack2(__float2half_rn(y[0][0]), __float2half_rn(y[0][1]));
                    hv.y = pack2(__float2half_rn(y[0][2]), __float2half_rn(y[0][3]));
                    hv.z = pack2(__float2half_rn(y[1][0]), __float2half_rn(y[1][1]));
                    hv.w = pack2(__float2half_rn(y[1][2]), __float2half_rn(y[1][3]));
                    *(uint4*)&AsH[(1 - p) * 2048 + m2 * 1024 + ns * 128 + lane * 4] = hv;

                    if (l == NL - 1 && t == T - 1) {
#pragma unroll
                        for (int nt = 0; nt < 2; ++nt) {
                            int c0 = ns * 16 + nt * 8 + 2 * tig;
                            hsm[m2 * 16 + grp][c0]         = y[nt][0];
                            hsm[m2 * 16 + grp][c0 + 1]     = y[nt][1];
                            hsm[m2 * 16 + grp + 8][c0]     = y[nt][2];
                            hsm[m2 * 16 + grp + 8][c0 + 1] = y[nt][3];
                        }
                    }
                }
            } else if (l < NL - 1 && t > 0) {
                // ---- proj: xp_{l+1}[t-1] = h_{t-1} @ Wih_{l+1}^T + b ----
                float acc[2][2][4];
#pragma unroll
                for (int m2 = 0; m2 < 2; ++m2)
#pragma unroll
                    for (int nt = 0; nt < 2; ++nt)
#pragma unroll
                        for (int j = 0; j < 4; ++j) acc[m2][nt][j] = bP[nt][j & 1];
#pragma unroll
                for (int kc = 0; kc < 8; ++kc) {
                    uint4 a0 = *(const uint4*)&AsH[p * 2048 + kc * 128 + lane * 4];
                    uint4 a1 = *(const uint4*)&AsH[p * 2048 + 1024 + kc * 128 + lane * 4];
#pragma unroll
                    for (int nt = 0; nt < 2; ++nt) {
                        mma16(acc[0][nt], a0, Bhi[kc][nt]);
                        mma16(acc[0][nt], a0, Blo[kc][nt]);
                        mma16(acc[1][nt], a1, Bhi[kc][nt]);
                        mma16(acc[1][nt], a1, Blo[kc][nt]);
                    }
                }
#pragma unroll
                for (int m2 = 0; m2 < 2; ++m2) {
                    float4* dst = (float4*)(xout + (size_t)(t - 1) * 4096 + m2 * 2048 + ns * 256 + lane * 8);
                    dst[0] = make_float4(acc[m2][0][0], acc[m2][0][1], acc[m2][0][2], acc[m2][0][3]);
                    dst[1] = make_float4(acc[m2][1][0], acc[m2][1][1], acc[m2][1][2], acc[m2][1][3]);
                }
            }
            __syncthreads();
            p ^= 1;
        }

        // tail: project h_{T-1} (in buf p)
        if (!scanw && l < NL - 1) {
            float acc[2][2][4];
#pragma unroll
            for (int m2 = 0; m2 < 2; ++m2)
#pragma unroll
                for (int nt = 0; nt < 2; ++nt)
#pragma unroll
                    for (int j = 0; j < 4; ++j) acc[m2][nt][j] = bP[nt][j & 1];
#pragma unroll
            for (int kc = 0; kc < 8; ++kc) {
                uint4 a0 = *(const uint4*)&AsH[p * 2048 + kc * 128 + lane * 4];
                uint4 a1 = *(const uint4*)&AsH[p * 2048 + 1024 + kc * 128 + lane * 4];
#pragma unroll
                for (int nt = 0; nt < 2; ++nt) {
                    mma16(acc[0][nt], a0, Bhi[kc][nt]);
                    mma16(acc[0][nt], a0, Blo[kc][nt]);
                    mma16(acc[1][nt], a1, Bhi[kc][nt]);
                    mma16(acc[1][nt], a1, Blo[kc][nt]);
                }
            }
#pragma unroll
            for (int m2 = 0; m2 < 2; ++m2) {
                float4* dst = (float4*)(xout + (size_t)(T - 1) * 4096 + m2 * 2048 + ns * 256 + lane * 8);
                dst[0] = make_float4(acc[m2][0][0], acc[m2][0][1], acc[m2][0][2], acc[m2][0][3]);
                dst[1] = make_float4(acc[m2][1][0], acc[m2][1][1], acc[m2][1][2], acc[m2][1][3]);
            }
        }
        __syncthreads();
    }

    // =======================================================================
    // FC head
    // =======================================================================
    if (tid < BT * NC) {
        int r = tid / NC, c = tid - r * NC;
        const float* wgt = fcW + c * H;
        float s = fcb[c];
#pragma unroll 8
        for (int k = 0; k < H; ++k) s += hsm[r][k] * wgt[k];
        out[(size_t)(b0 + r) * NC + c] = s;
    }
}

extern "C" void kernel_launch(void* const* d_in, const int* in_sizes, int n_in,
                              void* d_out, int out_size)
{
    const float* x    = (const float*)d_in[0];
    const float* Wih0 = (const float*)d_in[1];
    const float* Wih  = (const float*)d_in[2];
    const float* Whh  = (const float*)d_in[3];
    const float* bih  = (const float*)d_in[4];
    const float* bhh  = (const float*)d_in[5];
    const float* fcW  = (const float*)d_in[6];
    const float* fcb  = (const float*)d_in[7];
    float* out = (float*)d_out;

    float *xpA, *xpB;
    cudaGetSymbolAddress((void**)&xpA, g_xpA);
    cudaGetSymbolAddress((void**)&xpB, g_xpB);

    rnn_net<<<CTAS, NT>>>(x, Wih0, Wih, Whh, bih, bhh, fcW, fcb, out, xpA, xpB);
}

// round 10
// speedup vs baseline: 2.5696x; 1.2570x over previous
#include <cuda_runtime.h>
#include <cuda_fp16.h>
#include <stdint.h>

#define B  4096
#define T  28
#define H  128
#define F0 28
#define NL 10
#define NC 10
#define BT 32           // batch rows per CTA (two m16 tiles)
#define CTAS (B / BT)   // 128 -> single wave on 148 SMs
#define NT 512          // 16 warps: 0-7 scan, 8-15 projection

// Static device buffers (no allocation allowed). xp ping-pong, fragment order.
__device__ float g_xpA[(size_t)B * T * H];
__device__ float g_xpB[(size_t)B * T * H];

// ---------------------------------------------------------------------------
// helpers
// ---------------------------------------------------------------------------
__device__ __forceinline__ uint32_t pack2(__half a, __half b) {
    __half2 h = __halves2half2(a, b);
    return *reinterpret_cast<uint32_t*>(&h);
}
__device__ __forceinline__ void mma16(float c[4], uint4 a, const uint32_t b[2]) {
    asm volatile("mma.sync.aligned.m16n8k16.row.col.f32.f16.f16.f32 "
        "{%0,%1,%2,%3}, {%4,%5,%6,%7}, {%8,%9}, {%0,%1,%2,%3};"
        : "+f"(c[0]), "+f"(c[1]), "+f"(c[2]), "+f"(c[3])
        : "r"(a.x), "r"(a.y), "r"(a.z), "r"(a.w), "r"(b[0]), "r"(b[1]));
}
__device__ __forceinline__ float fast_tanh(float x) {
    float e; asm("ex2.approx.f32 %0, %1;" : "=f"(e) : "f"(x * 2.8853900817779268f));
    float r; asm("rcp.approx.f32 %0, %1;" : "=f"(r) : "f"(e + 1.0f));
    return fmaf(-2.0f, r, 1.0f);
}
// A-fragment word index for element (rl 0..15, kk 0..15) of one m16k16 tile
__device__ __forceinline__ int awidx(int rl, int kk) {
    int lane = ((rl & 7) << 2) | ((kk & 7) >> 1);
    int reg  = ((kk & 8) >> 2) | (rl >> 3);
    return lane * 4 + reg;               // half select = kk & 1
}

// ---------------------------------------------------------------------------
// Persistent whole-network kernel, warp-specialized, 2 m-tiles per warp:
//   scan warps (0-7):  h_t = tanh(xp_l[t] + h_{t-1} @ Whh_l^T)
//   proj warps (8-15): xp_{l+1}[t-1] = h_{t-1} @ Wih_{l+1}^T + b_{l+1}
// Pure fp16 operands (weights + activations), fp32 accumulate.
// ---------------------------------------------------------------------------
__global__ void __launch_bounds__(NT, 1)
rnn_net(const float* __restrict__ x,      // [B, T, F0]
        const float* __restrict__ Wih0,   // [H, F0]
        const float* __restrict__ WihR,   // [NL-1, H, H]
        const float* __restrict__ Whh,    // [NL, H, H]
        const float* __restrict__ bih,    // [NL, H]
        const float* __restrict__ bhh,    // [NL, H]
        const float* __restrict__ fcW,    // [NC, H]
        const float* __restrict__ fcb,    // [NC]
        float*       __restrict__ out,    // [B, NC]
        float*       __restrict__ xpA,
        float*       __restrict__ xpB)
{
    // h fragments: [buf][m2][kc][lane*4+reg]  (2*2*1024 words)
    __shared__ __align__(16) uint32_t AsH[4096];
    __shared__ float hsm[BT][H];

    const int tid  = threadIdx.x;
    const int lane = tid & 31;
    const int w    = tid >> 5;
    const bool scanw = (w < 8);
    const int ns   = w & 7;
    const int grp  = lane >> 2;
    const int tig  = lane & 3;
    const int b0   = blockIdx.x * BT;
    const size_t cta_off = (size_t)blockIdx.x * (T * 4096);
    float* xp0 = xpA + cta_off;
    float* xp1 = xpB + cta_off;

    // =======================================================================
    // PHASE A: xp0 = x @ Wih0^T + b_0.  Warp w -> tile (m2 = w>>3, ns).
    // =======================================================================
    {
        const int am2 = w >> 3;
        uint32_t Phi[2][2][2];
#pragma unroll
        for (int kc = 0; kc < 2; ++kc)
#pragma unroll
            for (int nt = 0; nt < 2; ++nt) {
                int n  = ns * 16 + nt * 8 + grp;
                int k0 = kc * 16 + 2 * tig;
                float v00 = (k0     < F0) ? Wih0[n * F0 + k0]     : 0.0f;
                float v01 = (k0 + 1 < F0) ? Wih0[n * F0 + k0 + 1] : 0.0f;
                float v10 = (k0 + 8 < F0) ? Wih0[n * F0 + k0 + 8] : 0.0f;
                float v11 = (k0 + 9 < F0) ? Wih0[n * F0 + k0 + 9] : 0.0f;
                Phi[kc][nt][0] = pack2(__float2half_rn(v00), __float2half_rn(v01));
                Phi[kc][nt][1] = pack2(__float2half_rn(v10), __float2half_rn(v11));
            }
        float bi0[2][2];
#pragma unroll
        for (int nt = 0; nt < 2; ++nt) {
            int c0 = ns * 16 + nt * 8 + 2 * tig;
            bi0[nt][0] = bih[c0]     + bhh[c0];
            bi0[nt][1] = bih[c0 + 1] + bhh[c0 + 1];
        }

        __half* AsHh = reinterpret_cast<__half*>(AsH);
        for (int t = 0; t < T; ++t) {
            for (int i = tid; i < 1024; i += NT) {
                int r = i >> 5, k = i & 31;
                float v = (k < F0)
                    ? x[((size_t)(b0 + r) * T + t) * F0 + k] : 0.0f;
                int word = (r >> 4) * 1024 + (k >> 4) * 128 + awidx(r & 15, k & 15);
                AsHh[2 * word + (k & 1)] = __float2half_rn(v);
            }
            __syncthreads();
            {
                float acc[2][4];
#pragma unroll
                for (int nt = 0; nt < 2; ++nt)
#pragma unroll
                    for (int j = 0; j < 4; ++j) acc[nt][j] = bi0[nt][j & 1];
#pragma unroll
                for (int kc = 0; kc < 2; ++kc) {
                    uint4 ah = *(const uint4*)&AsH[am2 * 1024 + kc * 128 + lane * 4];
#pragma unroll
                    for (int nt = 0; nt < 2; ++nt)
                        mma16(acc[nt], ah, Phi[kc][nt]);
                }
                float4* dst = (float4*)(xp0 + (size_t)t * 4096 + am2 * 2048 + ns * 256 + lane * 8);
                dst[0] = make_float4(acc[0][0], acc[0][1], acc[0][2], acc[0][3]);
                dst[1] = make_float4(acc[1][0], acc[1][1], acc[1][2], acc[1][3]);
            }
            __syncthreads();
        }
    }

    // =======================================================================
    // MAIN: 10 fused scan+projection layers
    // =======================================================================
    uint32_t Bw[8][2][2];   // role weight fragments (single fp16)
    float bP[2][2];         // proj bias (layer l+1)

    for (int l = 0; l < NL; ++l) {
        const float* xin  = (l & 1) ? xp1 : xp0;
        float*       xout = (l & 1) ? xp0 : xp1;

        {
            const float* Wsel = scanw ? (Whh + (size_t)l * H * H)
                                      : (l < NL - 1 ? WihR + (size_t)l * H * H : nullptr);
            if (Wsel) {
#pragma unroll
                for (int kc = 0; kc < 8; ++kc)
#pragma unroll
                    for (int nt = 0; nt < 2; ++nt) {
                        int n  = ns * 16 + nt * 8 + grp;
                        int k0 = kc * 16 + 2 * tig;
                        Bw[kc][nt][0] = pack2(__float2half_rn(Wsel[n * H + k0]),
                                              __float2half_rn(Wsel[n * H + k0 + 1]));
                        Bw[kc][nt][1] = pack2(__float2half_rn(Wsel[n * H + k0 + 8]),
                                              __float2half_rn(Wsel[n * H + k0 + 9]));
                    }
            }
            if (!scanw && l < NL - 1) {
                const float* bi = bih + (size_t)(l + 1) * H;
                const float* bh = bhh + (size_t)(l + 1) * H;
#pragma unroll
                for (int nt = 0; nt < 2; ++nt) {
                    int c0 = ns * 16 + nt * 8 + 2 * tig;
                    bP[nt][0] = bi[c0]     + bh[c0];
                    bP[nt][1] = bi[c0 + 1] + bh[c0 + 1];
                }
            }
        }

        // zero h buffer 0 (h_{-1} = 0)
        for (int i = tid; i < 2048; i += NT) AsH[i] = 0u;
        __syncthreads();

        int p = 0;
        float4 xv00, xv01, xv10, xv11;
        if (scanw) {
            const float4* s0 = (const float4*)(xin + ns * 256 + lane * 8);
            const float4* s1 = (const float4*)(xin + 2048 + ns * 256 + lane * 8);
            xv00 = s0[0]; xv01 = s0[1]; xv10 = s1[0]; xv11 = s1[1];
        }

        for (int t = 0; t < T; ++t) {
            if (scanw) {
                // ---- scan: h_t = tanh(xp[t] + h_{t-1} @ Whh^T), 2 m-tiles ----
                float acc[2][2][4];     // [m2][nt][4]
                acc[0][0][0] = xv00.x; acc[0][0][1] = xv00.y; acc[0][0][2] = xv00.z; acc[0][0][3] = xv00.w;
                acc[0][1][0] = xv01.x; acc[0][1][1] = xv01.y; acc[0][1][2] = xv01.z; acc[0][1][3] = xv01.w;
                acc[1][0][0] = xv10.x; acc[1][0][1] = xv10.y; acc[1][0][2] = xv10.z; acc[1][0][3] = xv10.w;
                acc[1][1][0] = xv11.x; acc[1][1][1] = xv11.y; acc[1][1][2] = xv11.z; acc[1][1][3] = xv11.w;
                if (t + 1 < T) {
                    const float4* n0 = (const float4*)(xin + (size_t)(t + 1) * 4096 + ns * 256 + lane * 8);
                    const float4* n1 = (const float4*)(xin + (size_t)(t + 1) * 4096 + 2048 + ns * 256 + lane * 8);
                    xv00 = n0[0]; xv01 = n0[1]; xv10 = n1[0]; xv11 = n1[1];
                }
#pragma unroll
                for (int kc = 0; kc < 8; ++kc) {
                    uint4 a0 = *(const uint4*)&AsH[p * 2048 + kc * 128 + lane * 4];
                    uint4 a1 = *(const uint4*)&AsH[p * 2048 + 1024 + kc * 128 + lane * 4];
#pragma unroll
                    for (int nt = 0; nt < 2; ++nt) {
                        mma16(acc[0][nt], a0, Bw[kc][nt]);
                        mma16(acc[1][nt], a1, Bw[kc][nt]);
                    }
                }
#pragma unroll
                for (int m2 = 0; m2 < 2; ++m2) {
                    float y[2][4];
#pragma unroll
                    for (int nt = 0; nt < 2; ++nt)
#pragma unroll
                        for (int j = 0; j < 4; ++j)
                            y[nt][j] = fast_tanh(acc[m2][nt][j]);
                    uint4 hv;
                    hv.x = pack2(__float2half_rn(y[0][0]), __float2half_rn(y[0][1]));
                    hv.y = pack2(__float2half_rn(y[0][2]), __float2half_rn(y[0][3]));
                    hv.z = pack2(__float2half_rn(y[1][0]), __float2half_rn(y[1][1]));
                    hv.w = pack2(__float2half_rn(y[1][2]), __float2half_rn(y[1][3]));
                    *(uint4*)&AsH[(1 - p) * 2048 + m2 * 1024 + ns * 128 + lane * 4] = hv;

                    if (l == NL - 1 && t == T - 1) {
#pragma unroll
                        for (int nt = 0; nt < 2; ++nt) {
                            int c0 = ns * 16 + nt * 8 + 2 * tig;
                            hsm[m2 * 16 + grp][c0]         = y[nt][0];
                            hsm[m2 * 16 + grp][c0 + 1]     = y[nt][1];
                            hsm[m2 * 16 + grp + 8][c0]     = y[nt][2];
                            hsm[m2 * 16 + grp + 8][c0 + 1] = y[nt][3];
                        }
                    }
                }
            } else if (l < NL - 1 && t > 0) {
                // ---- proj: xp_{l+1}[t-1] = h_{t-1} @ Wih_{l+1}^T + b ----
                float acc[2][2][4];
#pragma unroll
                for (int m2 = 0; m2 < 2; ++m2)
#pragma unroll
                    for (int nt = 0; nt < 2; ++nt)
#pragma unroll
                        for (int j = 0; j < 4; ++j) acc[m2][nt][j] = bP[nt][j & 1];
#pragma unroll
                for (int kc = 0; kc < 8; ++kc) {
                    uint4 a0 = *(const uint4*)&AsH[p * 2048 + kc * 128 + lane * 4];
                    uint4 a1 = *(const uint4*)&AsH[p * 2048 + 1024 + kc * 128 + lane * 4];
#pragma unroll
                    for (int nt = 0; nt < 2; ++nt) {
                        mma16(acc[0][nt], a0, Bw[kc][nt]);
                        mma16(acc[1][nt], a1, Bw[kc][nt]);
                    }
                }
#pragma unroll
                for (int m2 = 0; m2 < 2; ++m2) {
                    float4* dst = (float4*)(xout + (size_t)(t - 1) * 4096 + m2 * 2048 + ns * 256 + lane * 8);
                    dst[0] = make_float4(acc[m2][0][0], acc[m2][0][1], acc[m2][0][2], acc[m2][0][3]);
                    dst[1] = make_float4(acc[m2][1][0], acc[m2][1][1], acc[m2][1][2], acc[m2][1][3]);
                }
            }
            __syncthreads();
            p ^= 1;
        }

        // tail: project h_{T-1} (in buf p)
        if (!scanw && l < NL - 1) {
            float acc[2][2][4];
#pragma unroll
            for (int m2 = 0; m2 < 2; ++m2)
#pragma unroll
                for (int nt = 0; nt < 2; ++nt)
#pragma unroll
                    for (int j = 0; j < 4; ++j) acc[m2][nt][j] = bP[nt][j & 1];
#pragma unroll
            for (int kc = 0; kc < 8; ++kc) {
                uint4 a0 = *(const uint4*)&AsH[p * 2048 + kc * 128 + lane * 4];
                uint4 a1 = *(const uint4*)&AsH[p * 2048 + 1024 + kc * 128 + lane * 4];
#pragma unroll
                for (int nt = 0; nt < 2; ++nt) {
                    mma16(acc[0][nt], a0, Bw[kc][nt]);
                    mma16(acc[1][nt], a1, Bw[kc][nt]);
                }
            }
#pragma unroll
            for (int m2 = 0; m2 < 2; ++m2) {
                float4* dst = (float4*)(xout + (size_t)(T - 1) * 4096 + m2 * 2048 + ns * 256 + lane * 8);
                dst[0] = make_float4(acc[m2][0][0], acc[m2][0][1], acc[m2][0][2], acc[m2][0][3]);
                dst[1] = make_float4(acc[m2][1][0], acc[m2][1][1], acc[m2][1][2], acc[m2][1][3]);
            }
        }
        __syncthreads();
    }

    // =======================================================================
    // FC head
    // =======================================================================
    if (tid < BT * NC) {
        int r = tid / NC, c = tid - r * NC;
        const float* wgt = fcW + c * H;
        float s = fcb[c];
#pragma unroll 8
        for (int k = 0; k < H; ++k) s += hsm[r][k] * wgt[k];
        out[(size_t)(b0 + r) * NC + c] = s;
    }
}

extern "C" void kernel_launch(void* const* d_in, const int* in_sizes, int n_in,
                              void* d_out, int out_size)
{
    const float* x    = (const float*)d_in[0];
    const float* Wih0 = (const float*)d_in[1];
    const float* Wih  = (const float*)d_in[2];
    const float* Whh  = (const float*)d_in[3];
    const float* bih  = (const float*)d_in[4];
    const float* bhh  = (const float*)d_in[5];
    const float* fcW  = (const float*)d_in[6];
    const float* fcb  = (const float*)d_in[7];
    float* out = (float*)d_out;

    float *xpA, *xpB;
    cudaGetSymbolAddress((void**)&xpA, g_xpA);
    cudaGetSymbolAddress((void**)&xpB, g_xpB);

    rnn_net<<<CTAS, NT>>>(x, Wih0, Wih, Whh, bih, bhh, fcW, fcb, out, xpA, xpB);
}

// round 11
// speedup vs baseline: 2.7046x; 1.0525x over previous
#include <cuda_runtime.h>
#include <cuda_fp16.h>
#include <stdint.h>

#define B  4096
#define T  28
#define H  128
#define F0 28
#define NL 10
#define NC 10
#define BT 32           // batch rows per CTA (two m16 tiles)
#define CTAS (B / BT)   // 128 -> single wave on 148 SMs
#define NT 512          // 16 warps: 0-7 scan, 8-15 projection

// Static device buffers (no allocation allowed). xp ping-pong, fragment order.
__device__ float g_xpA[(size_t)B * T * H];
__device__ float g_xpB[(size_t)B * T * H];

// ---------------------------------------------------------------------------
// helpers
// ---------------------------------------------------------------------------
// pack two fp32 into half2 word (lo -> low half) in ONE instruction
__device__ __forceinline__ uint32_t cvt_pack(float lo, float hi) {
    uint32_t r; asm("cvt.rn.f16x2.f32 %0, %1, %2;" : "=r"(r) : "f"(hi), "f"(lo));
    return r;
}
// hardware tanh (sm_75+), single MUFU op, max rel err ~2^-11
__device__ __forceinline__ float tanh32(float x) {
    float r; asm("tanh.approx.f32 %0, %1;" : "=f"(r) : "f"(x));
    return r;
}
__device__ __forceinline__ void mma16(float c[4], uint4 a, const uint32_t b[2]) {
    asm volatile("mma.sync.aligned.m16n8k16.row.col.f32.f16.f16.f32 "
        "{%0,%1,%2,%3}, {%4,%5,%6,%7}, {%8,%9}, {%0,%1,%2,%3};"
        : "+f"(c[0]), "+f"(c[1]), "+f"(c[2]), "+f"(c[3])
        : "r"(a.x), "r"(a.y), "r"(a.z), "r"(a.w), "r"(b[0]), "r"(b[1]));
}
// A-fragment word index for element (rl 0..15, kk 0..15) of one m16k16 tile
__device__ __forceinline__ int awidx(int rl, int kk) {
    int lane = ((rl & 7) << 2) | ((kk & 7) >> 1);
    int reg  = ((kk & 8) >> 2) | (rl >> 3);
    return lane * 4 + reg;               // half select = kk & 1
}

// ---------------------------------------------------------------------------
// Persistent whole-network kernel, warp-specialized, 2 m-tiles per warp:
//   scan warps (0-7):  h_t = tanh(xp_l[t] + h_{t-1} @ Whh_l^T)
//   proj warps (8-15): xp_{l+1}[t-1] = h_{t-1} @ Wih_{l+1}^T + b_{l+1}
// fp16 operands, fp32 accumulate, MUFU.TANH + single-instr f16x2 pack epilogue.
// ---------------------------------------------------------------------------
__global__ void __launch_bounds__(NT, 1)
rnn_net(const float* __restrict__ x,      // [B, T, F0]
        const float* __restrict__ Wih0,   // [H, F0]
        const float* __restrict__ WihR,   // [NL-1, H, H]
        const float* __restrict__ Whh,    // [NL, H, H]
        const float* __restrict__ bih,    // [NL, H]
        const float* __restrict__ bhh,    // [NL, H]
        const float* __restrict__ fcW,    // [NC, H]
        const float* __restrict__ fcb,    // [NC]
        float*       __restrict__ out,    // [B, NC]
        float*       __restrict__ xpA,
        float*       __restrict__ xpB)
{
    // h fragments: [buf][m2][kc][lane*4+reg]  (2*2*1024 words)
    __shared__ __align__(16) uint32_t AsH[4096];
    __shared__ float hsm[BT][H];

    const int tid  = threadIdx.x;
    const int lane = tid & 31;
    const int w    = tid >> 5;
    const bool scanw = (w < 8);
    const int ns   = w & 7;
    const int grp  = lane >> 2;
    const int tig  = lane & 3;
    const int b0   = blockIdx.x * BT;
    const size_t cta_off = (size_t)blockIdx.x * (T * 4096);
    float* xp0 = xpA + cta_off;
    float* xp1 = xpB + cta_off;

    // =======================================================================
    // PHASE A: xp0 = x @ Wih0^T + b_0.  Warp w -> tile (m2 = w>>3, ns).
    // =======================================================================
    {
        const int am2 = w >> 3;
        uint32_t Phi[2][2][2];
#pragma unroll
        for (int kc = 0; kc < 2; ++kc)
#pragma unroll
            for (int nt = 0; nt < 2; ++nt) {
                int n  = ns * 16 + nt * 8 + grp;
                int k0 = kc * 16 + 2 * tig;
                float v00 = (k0     < F0) ? Wih0[n * F0 + k0]     : 0.0f;
                float v01 = (k0 + 1 < F0) ? Wih0[n * F0 + k0 + 1] : 0.0f;
                float v10 = (k0 + 8 < F0) ? Wih0[n * F0 + k0 + 8] : 0.0f;
                float v11 = (k0 + 9 < F0) ? Wih0[n * F0 + k0 + 9] : 0.0f;
                Phi[kc][nt][0] = cvt_pack(v00, v01);
                Phi[kc][nt][1] = cvt_pack(v10, v11);
            }
        float bi0[2][2];
#pragma unroll
        for (int nt = 0; nt < 2; ++nt) {
            int c0 = ns * 16 + nt * 8 + 2 * tig;
            bi0[nt][0] = bih[c0]     + bhh[c0];
            bi0[nt][1] = bih[c0 + 1] + bhh[c0 + 1];
        }

        __half* AsHh = reinterpret_cast<__half*>(AsH);
        for (int t = 0; t < T; ++t) {
            for (int i = tid; i < 1024; i += NT) {
                int r = i >> 5, k = i & 31;
                float v = (k < F0)
                    ? x[((size_t)(b0 + r) * T + t) * F0 + k] : 0.0f;
                int word = (r >> 4) * 1024 + (k >> 4) * 128 + awidx(r & 15, k & 15);
                AsHh[2 * word + (k & 1)] = __float2half_rn(v);
            }
            __syncthreads();
            {
                float acc[2][4];
#pragma unroll
                for (int nt = 0; nt < 2; ++nt)
#pragma unroll
                    for (int j = 0; j < 4; ++j) acc[nt][j] = bi0[nt][j & 1];
#pragma unroll
                for (int kc = 0; kc < 2; ++kc) {
                    uint4 ah = *(const uint4*)&AsH[am2 * 1024 + kc * 128 + lane * 4];
#pragma unroll
                    for (int nt = 0; nt < 2; ++nt)
                        mma16(acc[nt], ah, Phi[kc][nt]);
                }
                float4* dst = (float4*)(xp0 + (size_t)t * 4096 + am2 * 2048 + ns * 256 + lane * 8);
                dst[0] = make_float4(acc[0][0], acc[0][1], acc[0][2], acc[0][3]);
                dst[1] = make_float4(acc[1][0], acc[1][1], acc[1][2], acc[1][3]);
            }
            __syncthreads();
        }
    }

    // =======================================================================
    // MAIN: 10 fused scan+projection layers
    // =======================================================================
    uint32_t Bw[8][2][2];   // role weight fragments (fp16)
    float bP[2][2];         // proj bias (layer l+1)

    for (int l = 0; l < NL; ++l) {
        const float* xin  = (l & 1) ? xp1 : xp0;
        float*       xout = (l & 1) ? xp0 : xp1;

        {
            const float* Wsel = scanw ? (Whh + (size_t)l * H * H)
                                      : (l < NL - 1 ? WihR + (size_t)l * H * H : nullptr);
            if (Wsel) {
#pragma unroll
                for (int kc = 0; kc < 8; ++kc)
#pragma unroll
                    for (int nt = 0; nt < 2; ++nt) {
                        int n  = ns * 16 + nt * 8 + grp;
                        int k0 = kc * 16 + 2 * tig;
                        Bw[kc][nt][0] = cvt_pack(Wsel[n * H + k0],     Wsel[n * H + k0 + 1]);
                        Bw[kc][nt][1] = cvt_pack(Wsel[n * H + k0 + 8], Wsel[n * H + k0 + 9]);
                    }
            }
            if (!scanw && l < NL - 1) {
                const float* bi = bih + (size_t)(l + 1) * H;
                const float* bh = bhh + (size_t)(l + 1) * H;
#pragma unroll
                for (int nt = 0; nt < 2; ++nt) {
                    int c0 = ns * 16 + nt * 8 + 2 * tig;
                    bP[nt][0] = bi[c0]     + bh[c0];
                    bP[nt][1] = bi[c0 + 1] + bh[c0 + 1];
                }
            }
        }

        // zero h buffer 0 (h_{-1} = 0)
        for (int i = tid; i < 2048; i += NT) AsH[i] = 0u;
        __syncthreads();

        int p = 0;
        float4 xv00, xv01, xv10, xv11;
        if (scanw) {
            const float4* s0 = (const float4*)(xin + ns * 256 + lane * 8);
            const float4* s1 = (const float4*)(xin + 2048 + ns * 256 + lane * 8);
            xv00 = s0[0]; xv01 = s0[1]; xv10 = s1[0]; xv11 = s1[1];
        }

        for (int t = 0; t < T; ++t) {
            if (scanw) {
                // ---- scan: h_t = tanh(xp[t] + h_{t-1} @ Whh^T), 2 m-tiles ----
                float acc[2][2][4];     // [m2][nt][4]
                acc[0][0][0] = xv00.x; acc[0][0][1] = xv00.y; acc[0][0][2] = xv00.z; acc[0][0][3] = xv00.w;
                acc[0][1][0] = xv01.x; acc[0][1][1] = xv01.y; acc[0][1][2] = xv01.z; acc[0][1][3] = xv01.w;
                acc[1][0][0] = xv10.x; acc[1][0][1] = xv10.y; acc[1][0][2] = xv10.z; acc[1][0][3] = xv10.w;
                acc[1][1][0] = xv11.x; acc[1][1][1] = xv11.y; acc[1][1][2] = xv11.z; acc[1][1][3] = xv11.w;
                if (t + 1 < T) {
                    const float4* n0 = (const float4*)(xin + (size_t)(t + 1) * 4096 + ns * 256 + lane * 8);
                    const float4* n1 = (const float4*)(xin + (size_t)(t + 1) * 4096 + 2048 + ns * 256 + lane * 8);
                    xv00 = n0[0]; xv01 = n0[1]; xv10 = n1[0]; xv11 = n1[1];
                }
#pragma unroll
                for (int kc = 0; kc < 8; ++kc) {
                    uint4 a0 = *(const uint4*)&AsH[p * 2048 + kc * 128 + lane * 4];
                    uint4 a1 = *(const uint4*)&AsH[p * 2048 + 1024 + kc * 128 + lane * 4];
#pragma unroll
                    for (int nt = 0; nt < 2; ++nt) {
                        mma16(acc[0][nt], a0, Bw[kc][nt]);
                        mma16(acc[1][nt], a1, Bw[kc][nt]);
                    }
                }
#pragma unroll
                for (int m2 = 0; m2 < 2; ++m2) {
                    // MUFU.TANH + single-instruction f16x2 packs
                    float y00 = tanh32(acc[m2][0][0]), y01 = tanh32(acc[m2][0][1]);
                    float y02 = tanh32(acc[m2][0][2]), y03 = tanh32(acc[m2][0][3]);
                    float y10 = tanh32(acc[m2][1][0]), y11 = tanh32(acc[m2][1][1]);
                    float y12 = tanh32(acc[m2][1][2]), y13 = tanh32(acc[m2][1][3]);
                    uint4 hv;
                    hv.x = cvt_pack(y00, y01);
                    hv.y = cvt_pack(y02, y03);
                    hv.z = cvt_pack(y10, y11);
                    hv.w = cvt_pack(y12, y13);
                    *(uint4*)&AsH[(1 - p) * 2048 + m2 * 1024 + ns * 128 + lane * 4] = hv;

                    if (l == NL - 1 && t == T - 1) {
#pragma unroll
                        for (int nt = 0; nt < 2; ++nt) {
                            int c0 = ns * 16 + nt * 8 + 2 * tig;
                            float a = (nt == 0) ? y00 : y10;
                            float bb = (nt == 0) ? y01 : y11;
                            float cc = (nt == 0) ? y02 : y12;
                            float dd = (nt == 0) ? y03 : y13;
                            hsm[m2 * 16 + grp][c0]         = a;
                            hsm[m2 * 16 + grp][c0 + 1]     = bb;
                            hsm[m2 * 16 + grp + 8][c0]     = cc;
                            hsm[m2 * 16 + grp + 8][c0 + 1] = dd;
                        }
                    }
                }
            } else if (l < NL - 1 && t > 0) {
                // ---- proj: xp_{l+1}[t-1] = h_{t-1} @ Wih_{l+1}^T + b ----
                float acc[2][2][4];
#pragma unroll
                for (int m2 = 0; m2 < 2; ++m2)
#pragma unroll
                    for (int nt = 0; nt < 2; ++nt)
#pragma unroll
                        for (int j = 0; j < 4; ++j) acc[m2][nt][j] = bP[nt][j & 1];
#pragma unroll
                for (int kc = 0; kc < 8; ++kc) {
                    uint4 a0 = *(const uint4*)&AsH[p * 2048 + kc * 128 + lane * 4];
                    uint4 a1 = *(const uint4*)&AsH[p * 2048 + 1024 + kc * 128 + lane * 4];
#pragma unroll
                    for (int nt = 0; nt < 2; ++nt) {
                        mma16(acc[0][nt], a0, Bw[kc][nt]);
                        mma16(acc[1][nt], a1, Bw[kc][nt]);
                    }
                }
#pragma unroll
                for (int m2 = 0; m2 < 2; ++m2) {
                    float4* dst = (float4*)(xout + (size_t)(t - 1) * 4096 + m2 * 2048 + ns * 256 + lane * 8);
                    dst[0] = make_float4(acc[m2][0][0], acc[m2][0][1], acc[m2][0][2], acc[m2][0][3]);
                    dst[1] = make_float4(acc[m2][1][0], acc[m2][1][1], acc[m2][1][2], acc[m2][1][3]);
                }
            }
            __syncthreads();
            p ^= 1;
        }

        // tail: project h_{T-1} (in buf p)
        if (!scanw && l < NL - 1) {
            float acc[2][2][4];
#pragma unroll
            for (int m2 = 0; m2 < 2; ++m2)
#pragma unroll
                for (int nt = 0; nt < 2; ++nt)
#pragma unroll
                    for (int j = 0; j < 4; ++j) acc[m2][nt][j] = bP[nt][j & 1];
#pragma unroll
            for (int kc = 0; kc < 8; ++kc) {
                uint4 a0 = *(const uint4*)&AsH[p * 2048 + kc * 128 + lane * 4];
                uint4 a1 = *(const uint4*)&AsH[p * 2048 + 1024 + kc * 128 + lane * 4];
#pragma unroll
                for (int nt = 0; nt < 2; ++nt) {
                    mma16(acc[0][nt], a0, Bw[kc][nt]);
                    mma16(acc[1][nt], a1, Bw[kc][nt]);
                }
            }
#pragma unroll
            for (int m2 = 0; m2 < 2; ++m2) {
                float4* dst = (float4*)(xout + (size_t)(T - 1) * 4096 + m2 * 2048 + ns * 256 + lane * 8);
                dst[0] = make_float4(acc[m2][0][0], acc[m2][0][1], acc[m2][0][2], acc[m2][0][3]);
                dst[1] = make_float4(acc[m2][1][0], acc[m2][1][1], acc[m2][1][2], acc[m2][1][3]);
            }
        }
        __syncthreads();
    }

    // =======================================================================
    // FC head
    // =======================================================================
    if (tid < BT * NC) {
        int r = tid / NC, c = tid - r * NC;
        const float* wgt = fcW + c * H;
        float s = fcb[c];
#pragma unroll 8
        for (int k = 0; k < H; ++k) s += hsm[r][k] * wgt[k];
        out[(size_t)(b0 + r) * NC + c] = s;
    }
}

extern "C" void kernel_launch(void* const* d_in, const int* in_sizes, int n_in,
                              void* d_out, int out_size)
{
    const float* x    = (const float*)d_in[0];
    const float* Wih0 = (const float*)d_in[1];
    const float* Wih  = (const float*)d_in[2];
    const float* Whh  = (const float*)d_in[3];
    const float* bih  = (const float*)d_in[4];
    const float* bhh  = (const float*)d_in[5];
    const float* fcW  = (const float*)d_in[6];
    const float* fcb  = (const float*)d_in[7];
    float* out = (float*)d_out;

    float *xpA, *xpB;
    cudaGetSymbolAddress((void**)&xpA, g_xpA);
    cudaGetSymbolAddress((void**)&xpB, g_xpB);

    rnn_net<<<CTAS, NT>>>(x, Wih0, Wih, Whh, bih, bhh, fcW, fcb, out, xpA, xpB);
}